// round 2
// baseline (speedup 1.0000x reference)
#include <cuda_runtime.h>
#include <math.h>

// Problem constants (fixed by reference_code)
#define B_    4
#define S_    2048
#define H_    768
#define NSEG  256
#define NROWS 2048      // B * S/4
#define QPB   512       // queries per batch
#define HALF  1024      // S/2 mask boundary

// -------- scratch --------
__device__ float g_segsum [B_ * NSEG * H_];
__device__ float g_segproj[B_ * NSEG * H_];
__device__ float g_sdot   [B_ * NSEG * NSEG];
__device__ int   g_cnt    [B_ * NSEG];
__device__ int   g_first  [B_ * NSEG];
__device__ float g_loss   [NROWS];
__device__ int   g_corr   [NROWS];

// -------- packed fp32x2 helpers (Blackwell FFMA2 path) --------
__device__ __forceinline__ unsigned long long pack2(float x, float y) {
    unsigned long long r;
    asm("mov.b64 %0, {%1, %2};" : "=l"(r) : "f"(x), "f"(y));
    return r;
}
__device__ __forceinline__ void unpack2(unsigned long long v, float& x, float& y) {
    asm("mov.b64 {%0, %1}, %2;" : "=f"(x), "=f"(y) : "l"(v));
}
__device__ __forceinline__ void ffma2(unsigned long long& d,
                                      unsigned long long a,
                                      unsigned long long b) {
    asm("fma.rn.f32x2 %0, %1, %2, %0;" : "+l"(d) : "l"(a), "l"(b));
}

// ---------------------------------------------------------------------------
// K1: segmented sum over sorted indicator + unmasked counts / first-index
// grid (NSEG, B), block 192 (one float4 lane of H per thread)
// ---------------------------------------------------------------------------
__global__ __launch_bounds__(192) void k_segsum(const float* __restrict__ x,
                                                const int* __restrict__ ind) {
    const int v = blockIdx.x;
    const int b = blockIdx.y;
    const int* row = ind + b * S_;

    int lo, hi;
    { int l = 0, r = S_;
      while (l < r) { int m = (l + r) >> 1; if (row[m] < v) l = m + 1; else r = m; }
      lo = l; }
    { int l = lo, r = S_;
      while (l < r) { int m = (l + r) >> 1; if (row[m] <= v) l = m + 1; else r = m; }
      hi = l; }

    const int t = threadIdx.x;  // 0..191
    float4 acc = make_float4(0.f, 0.f, 0.f, 0.f);
    const float4* xp = (const float4*)(x + ((size_t)b * S_ + lo) * H_) + t;
    for (int i = lo; i < hi; i++) {
        float4 u = *xp; xp += H_ / 4;
        acc.x += u.x; acc.y += u.y; acc.z += u.z; acc.w += u.w;
    }
    ((float4*)(g_segsum + ((size_t)b * NSEG + v) * H_))[t] = acc;

    if (t == 0) {
        int lo2 = lo > HALF ? lo : HALF;
        int c   = hi - lo2; if (c < 0) c = 0;
        g_cnt  [b * NSEG + v] = c;
        g_first[b * NSEG + v] = lo2;
    }
}

// ---------------------------------------------------------------------------
// GEMM core: C[32 x 64] tile = A[32 x K] * B[64 x K]^T, fp32x2 FFMA2 path.
// 64 threads, 4x8 micro-tile per thread (accs held as 16 packed u64 pairs).
// ---------------------------------------------------------------------------
template<bool DO_TANH>
__device__ __forceinline__ void gemm_tile_32x64(
    const float* __restrict__ A,   // row-major, stride K
    const float* __restrict__ Bm,  // row-major, stride K (used as B^T)
    float* __restrict__ C,         // row-major, stride ldc
    const float* __restrict__ bias,
    int K, int ldc, int bm, int bn)
{
    __shared__ __align__(16) float As[16][32];
    __shared__ __align__(16) float Bs[16][64];

    const int tid = threadIdx.x;
    const int tx  = tid & 7;    // 8 col groups of 8
    const int ty  = tid >> 3;   // 8 row groups of 4

    unsigned long long acc[4][4];
    #pragma unroll
    for (int i = 0; i < 4; i++)
        #pragma unroll
        for (int j = 0; j < 4; j++) acc[i][j] = 0ull;

    const int arow = tid >> 1;          // 0..31
    const int ak0  = (tid & 1) * 2;     // which pair of float4 k-chunks

    for (int k0 = 0; k0 < K; k0 += 16) {
        // A: 32 rows x 16 k (2 float4 per thread, transposed into As[k][m])
        #pragma unroll
        for (int t = 0; t < 2; t++) {
            const int kq = ak0 + t;
            float4 a = *(const float4*)(A + (size_t)(bm + arow) * K + k0 + kq * 4);
            As[kq * 4 + 0][arow] = a.x;
            As[kq * 4 + 1][arow] = a.y;
            As[kq * 4 + 2][arow] = a.z;
            As[kq * 4 + 3][arow] = a.w;
        }
        // B: 64 rows x 16 k (4 float4 per thread = one full row chunk)
        #pragma unroll
        for (int t = 0; t < 4; t++) {
            float4 w = *(const float4*)(Bm + (size_t)(bn + tid) * K + k0 + t * 4);
            Bs[t * 4 + 0][tid] = w.x;
            Bs[t * 4 + 1][tid] = w.y;
            Bs[t * 4 + 2][tid] = w.z;
            Bs[t * 4 + 3][tid] = w.w;
        }
        __syncthreads();

        #pragma unroll
        for (int kk = 0; kk < 16; kk++) {
            float4 a4 = *(const float4*)&As[kk][ty << 2];
            ulonglong2 b0 = *(const ulonglong2*)&Bs[kk][tx << 3];
            ulonglong2 b1 = *(const ulonglong2*)&Bs[kk][(tx << 3) + 4];
            unsigned long long ap0 = pack2(a4.x, a4.x);
            unsigned long long ap1 = pack2(a4.y, a4.y);
            unsigned long long ap2 = pack2(a4.z, a4.z);
            unsigned long long ap3 = pack2(a4.w, a4.w);
            ffma2(acc[0][0], ap0, b0.x); ffma2(acc[0][1], ap0, b0.y);
            ffma2(acc[0][2], ap0, b1.x); ffma2(acc[0][3], ap0, b1.y);
            ffma2(acc[1][0], ap1, b0.x); ffma2(acc[1][1], ap1, b0.y);
            ffma2(acc[1][2], ap1, b1.x); ffma2(acc[1][3], ap1, b1.y);
            ffma2(acc[2][0], ap2, b0.x); ffma2(acc[2][1], ap2, b0.y);
            ffma2(acc[2][2], ap2, b1.x); ffma2(acc[2][3], ap2, b1.y);
            ffma2(acc[3][0], ap3, b0.x); ffma2(acc[3][1], ap3, b0.y);
            ffma2(acc[3][2], ap3, b1.x); ffma2(acc[3][3], ap3, b1.y);
        }
        __syncthreads();
    }

    const int row0 = bm + (ty << 2);
    const int col0 = bn + (tx << 3);
    float bv[8];
    if (DO_TANH) {
        #pragma unroll
        for (int j = 0; j < 8; j++) bv[j] = bias[col0 + j];
    }
    #pragma unroll
    for (int i = 0; i < 4; i++) {
        float o[8];
        #pragma unroll
        for (int j = 0; j < 4; j++) unpack2(acc[i][j], o[2 * j], o[2 * j + 1]);
        if (DO_TANH) {
            #pragma unroll
            for (int j = 0; j < 8; j++) o[j] = tanhf(o[j] + bv[j]);
        }
        float* cp = C + (size_t)(row0 + i) * ldc + col0;
        *(float4*)(cp + 0) = make_float4(o[0], o[1], o[2], o[3]);
        *(float4*)(cp + 4) = make_float4(o[4], o[5], o[6], o[7]);
    }
}

// K2: segproj = tanh(segsum @ W^T + b).  grid (768/64, 1024/32) = (12, 32)
__global__ __launch_bounds__(64) void k_proj(const float* __restrict__ W,
                                             const float* __restrict__ bias) {
    gemm_tile_32x64<true>(g_segsum, W, g_segproj, bias,
                          H_, H_, blockIdx.y * 32, blockIdx.x * 64);
}

// K3: Sdot[b] = P[b] @ P[b]^T, rows pruned to q <= qmax = ind[b,511].
// grid (256/64, 256/32, B) = (4, 8, 4)
__global__ __launch_bounds__(64) void k_sdot(const int* __restrict__ ind) {
    const int b  = blockIdx.z;
    const int bm = blockIdx.y * 32;
    const int qmax = ind[b * S_ + QPB - 1];
    if (bm > qmax) return;   // rows beyond max query are never read
    const float* P = g_segproj + (size_t)b * NSEG * H_;
    float*       C = g_sdot    + (size_t)b * NSEG * NSEG;
    gemm_tile_32x64<false>(P, P, C, nullptr,
                           H_, NSEG, bm, blockIdx.x * 64);
}

// ---------------------------------------------------------------------------
// K4: per query row: masked logsumexp + argmax over 256 segments
// one warp per row; 8 warps per block share batch b -> smem-cached cnt/first
// ---------------------------------------------------------------------------
__global__ __launch_bounds__(256) void k_rows(const int* __restrict__ ind,
                                              const int* __restrict__ clc) {
    __shared__ int s_cnt[NSEG];
    __shared__ int s_fst[NSEG];
    const int lane = threadIdx.x & 31;
    const int gw   = blockIdx.x * 8 + (threadIdx.x >> 5);   // row id
    const int b    = gw >> 9;
    const int i    = gw & (QPB - 1);

    if (threadIdx.x < NSEG) {
        s_cnt[threadIdx.x] = g_cnt  [b * NSEG + threadIdx.x];
        s_fst[threadIdx.x] = g_first[b * NSEG + threadIdx.x];
    }
    __syncthreads();

    const int q     = ind[b * S_ + i];
    const int label = clc[b * S_ + i];
    const float* srow = g_sdot + ((size_t)b * NSEG + q) * NSEG;

    float s[8]; int c[8];
    #pragma unroll
    for (int t = 0; t < 8; t++) {
        int v = lane + 32 * t;
        s[t] = srow[v];
        c[t] = s_cnt[v];
    }

    float bmax = -INFINITY; int bj = 0x7fffffff;
    #pragma unroll
    for (int t = 0; t < 8; t++) {
        if (c[t] > 0) {
            int j = s_fst[lane + 32 * t];
            if (s[t] > bmax || (s[t] == bmax && j < bj)) { bmax = s[t]; bj = j; }
        }
    }
    #pragma unroll
    for (int off = 16; off; off >>= 1) {
        float os = __shfl_xor_sync(0xffffffffu, bmax, off);
        int   oj = __shfl_xor_sync(0xffffffffu, bj,   off);
        if (os > bmax || (os == bmax && oj < bj)) { bmax = os; bj = oj; }
    }

    float z = 0.0f;
    #pragma unroll
    for (int t = 0; t < 8; t++)
        if (c[t] > 0) z += (float)c[t] * expf(s[t] - bmax);
    #pragma unroll
    for (int off = 16; off; off >>= 1)
        z += __shfl_xor_sync(0xffffffffu, z, off);

    if (lane == 0) {
        int vlab = ind[b * S_ + label];
        float slab = srow[vlab];
        float loss = (logf(z) + bmax) - slab;
        if (label < HALF) loss += 1.0e9f;
        g_loss[gw] = loss;
        g_corr[gw] = (bj == label) ? 1 : 0;
    }
}

// ---------------------------------------------------------------------------
// K5: final reduction -> 6 scalars (sep = even rows, tok = odd rows)
// ---------------------------------------------------------------------------
__global__ __launch_bounds__(256) void k_final(float* __restrict__ out) {
    __shared__ double sls[256], slt[256];
    __shared__ int    scs[256], sct[256];
    const int t = threadIdx.x;
    double ls = 0.0, lt = 0.0;
    int cs = 0, ct = 0;
    for (int r = t; r < NROWS; r += 256) {
        if (r & 1) { lt += (double)g_loss[r]; ct += g_corr[r]; }
        else       { ls += (double)g_loss[r]; cs += g_corr[r]; }
    }
    sls[t] = ls; slt[t] = lt; scs[t] = cs; sct[t] = ct;
    __syncthreads();
    for (int off = 128; off; off >>= 1) {
        if (t < off) {
            sls[t] += sls[t + off]; slt[t] += slt[t + off];
            scs[t] += scs[t + off]; sct[t] += sct[t + off];
        }
        __syncthreads();
    }
    if (t == 0) {
        const double n = (double)(NROWS / 2);
        out[0] = (float)(sls[0] / n);
        out[1] = (float)scs[0];
        out[2] = (float)(n + 1e-6);
        out[3] = (float)(slt[0] / n);
        out[4] = (float)sct[0];
        out[5] = (float)(n + 1e-6);
    }
}

// ---------------------------------------------------------------------------
extern "C" void kernel_launch(void* const* d_in, const int* in_sizes, int n_in,
                              void* d_out, int out_size) {
    const float* x    = (const float*)d_in[0];
    const float* W    = (const float*)d_in[1];
    const float* bias = (const float*)d_in[2];
    const int*   ind  = (const int*)  d_in[3];
    const int*   clc  = (const int*)  d_in[4];
    float* out = (float*)d_out;
    (void)in_sizes; (void)n_in; (void)out_size;

    dim3 g1(NSEG, B_);
    k_segsum<<<g1, 192>>>(x, ind);

    dim3 g2(H_ / 64, (B_ * NSEG) / 32);          // (12, 32) = 384 blocks
    k_proj<<<g2, 64>>>(W, bias);

    dim3 g3(NSEG / 64, NSEG / 32, B_);           // (4, 8, 4) = 128 blocks
    k_sdot<<<g3, 64>>>(ind);

    k_rows<<<NROWS / 8, 256>>>(ind, clc);

    k_final<<<1, 256>>>(out);
}

// round 3
// speedup vs baseline: 1.3222x; 1.3222x over previous
#include <cuda_runtime.h>
#include <math.h>

#define B_    4
#define S_    2048
#define H_    768
#define NSEG  256
#define NROWS 2048
#define QPB   512
#define HALF  1024

// -------- scratch --------
__device__ float g_segsum [B_ * NSEG * H_];
__device__ float g_segproj[B_ * NSEG * H_];
__device__ float g_sdot   [B_ * NSEG * NSEG];
__device__ float g_part   [3 * B_ * NSEG * H_];        // proj split-K partials (9MB)
__device__ float g_spart  [6 * B_ * NSEG * NSEG];      // sdot split-K partials (6MB)
__device__ int   g_cnt    [B_ * NSEG];
__device__ int   g_first  [B_ * NSEG];
__device__ float g_loss   [NROWS];
__device__ int   g_corr   [NROWS];

typedef unsigned long long u64;

__device__ __forceinline__ void unpack2(u64 v, float& x, float& y) {
    asm("mov.b64 {%0, %1}, %2;" : "=f"(x), "=f"(y) : "l"(v));
}
__device__ __forceinline__ void ffma2(u64& d, u64 a, u64 b) {
    asm("fma.rn.f32x2 %0, %1, %2, %0;" : "+l"(d) : "l"(a), "l"(b));
}

// ---------------------------------------------------------------------------
// K1: segmented sum over sorted indicator + unmasked counts / first-index
// ---------------------------------------------------------------------------
__global__ __launch_bounds__(192) void k_segsum(const float* __restrict__ x,
                                                const int* __restrict__ ind) {
    const int v = blockIdx.x;
    const int b = blockIdx.y;
    const int* row = ind + b * S_;

    int lo, hi;
    { int l = 0, r = S_;
      while (l < r) { int m = (l + r) >> 1; if (row[m] < v) l = m + 1; else r = m; }
      lo = l; }
    { int l = lo, r = S_;
      while (l < r) { int m = (l + r) >> 1; if (row[m] <= v) l = m + 1; else r = m; }
      hi = l; }

    const int t = threadIdx.x;
    float4 acc = make_float4(0.f, 0.f, 0.f, 0.f);
    const float4* xp = (const float4*)(x + ((size_t)b * S_ + lo) * H_) + t;
    for (int i = lo; i < hi; i++) {
        float4 u = *xp; xp += H_ / 4;
        acc.x += u.x; acc.y += u.y; acc.z += u.z; acc.w += u.w;
    }
    ((float4*)(g_segsum + ((size_t)b * NSEG + v) * H_))[t] = acc;

    if (t == 0) {
        int lo2 = lo > HALF ? lo : HALF;
        int c   = hi - lo2; if (c < 0) c = 0;
        g_cnt  [b * NSEG + v] = c;
        g_first[b * NSEG + v] = lo2;
    }
}

// ---------------------------------------------------------------------------
// GEMM tile: Cpart[64 x 128] += A[64 x Kslice] * B[128 x Kslice]^T  (fp32x2)
// 256 threads, micro 4x8 per thread = 16 FFMA2 accs.
// A stored DUPLICATED in smem ((a,a) pairs) so FFMA2 broadcasts need no MOVs.
// ---------------------------------------------------------------------------
__device__ __forceinline__ void gemm64x128(
    const float* A, const float* Bm, float* Cpart,
    int Ks, int k_begin, int k_end, int ldc, int bm, int bn)
{
    __shared__ __align__(16) float AsD[16][128];  // [k][2*m] duplicated pairs
    __shared__ __align__(16) float Bs [16][128];  // [k][n]

    const int tid = threadIdx.x;
    const int tx  = tid & 15;        // N group (8 cols)
    const int ty  = tid >> 4;        // M group (4 rows)
    const int ar  = tid >> 2;        // A staging row 0..63
    const int ak  = (tid & 3) << 2;  // A staging k offset
    const int br  = tid >> 1;        // B staging row 0..127
    const int bk  = (tid & 1) << 3;  // B staging k offset (0 or 8)

    u64 acc[4][4];
    #pragma unroll
    for (int i = 0; i < 4; i++)
        #pragma unroll
        for (int j = 0; j < 4; j++) acc[i][j] = 0ull;

    for (int k0 = k_begin; k0 < k_end; k0 += 16) {
        float4 a = *(const float4*)(A + (size_t)(bm + ar) * Ks + k0 + ak);
        ((float2*)AsD[ak + 0])[ar] = make_float2(a.x, a.x);
        ((float2*)AsD[ak + 1])[ar] = make_float2(a.y, a.y);
        ((float2*)AsD[ak + 2])[ar] = make_float2(a.z, a.z);
        ((float2*)AsD[ak + 3])[ar] = make_float2(a.w, a.w);

        float4 b0 = *(const float4*)(Bm + (size_t)(bn + br) * Ks + k0 + bk);
        float4 b1 = *(const float4*)(Bm + (size_t)(bn + br) * Ks + k0 + bk + 4);
        Bs[bk + 0][br] = b0.x; Bs[bk + 1][br] = b0.y;
        Bs[bk + 2][br] = b0.z; Bs[bk + 3][br] = b0.w;
        Bs[bk + 4][br] = b1.x; Bs[bk + 5][br] = b1.y;
        Bs[bk + 6][br] = b1.z; Bs[bk + 7][br] = b1.w;
        __syncthreads();

        #pragma unroll
        for (int kk = 0; kk < 16; kk++) {
            ulonglong2 aa0 = *(const ulonglong2*)&AsD[kk][ty << 3];
            ulonglong2 aa1 = *(const ulonglong2*)&AsD[kk][(ty << 3) + 4];
            ulonglong2 bb0 = *(const ulonglong2*)&Bs [kk][tx << 3];
            ulonglong2 bb1 = *(const ulonglong2*)&Bs [kk][(tx << 3) + 4];
            ffma2(acc[0][0], aa0.x, bb0.x); ffma2(acc[0][1], aa0.x, bb0.y);
            ffma2(acc[0][2], aa0.x, bb1.x); ffma2(acc[0][3], aa0.x, bb1.y);
            ffma2(acc[1][0], aa0.y, bb0.x); ffma2(acc[1][1], aa0.y, bb0.y);
            ffma2(acc[1][2], aa0.y, bb1.x); ffma2(acc[1][3], aa0.y, bb1.y);
            ffma2(acc[2][0], aa1.x, bb0.x); ffma2(acc[2][1], aa1.x, bb0.y);
            ffma2(acc[2][2], aa1.x, bb1.x); ffma2(acc[2][3], aa1.x, bb1.y);
            ffma2(acc[3][0], aa1.y, bb0.x); ffma2(acc[3][1], aa1.y, bb0.y);
            ffma2(acc[3][2], aa1.y, bb1.x); ffma2(acc[3][3], aa1.y, bb1.y);
        }
        __syncthreads();
    }

    const int col0 = bn + (tx << 3);
    #pragma unroll
    for (int i = 0; i < 4; i++) {
        float o[8];
        #pragma unroll
        for (int j = 0; j < 4; j++) unpack2(acc[i][j], o[2 * j], o[2 * j + 1]);
        float* cp = Cpart + (size_t)(bm + (ty << 2) + i) * ldc + col0;
        *(float4*)(cp + 0) = make_float4(o[0], o[1], o[2], o[3]);
        *(float4*)(cp + 4) = make_float4(o[4], o[5], o[6], o[7]);
    }
}

// K2a: proj partials. grid (768/128, 1024/64, 3 splits) = (6,16,3)=288 blocks
__global__ __launch_bounds__(256) void k_proj(const float* __restrict__ W) {
    const int ks = blockIdx.z;
    gemm64x128(g_segsum, W, g_part + (size_t)ks * (B_ * NSEG * H_),
               H_, ks * 256, ks * 256 + 256, H_,
               blockIdx.y * 64, blockIdx.x * 128);
}

// K2b: segproj = tanh(sum of 3 partials + bias)
__global__ __launch_bounds__(256) void k_proj_fix(const float* __restrict__ bias) {
    const int i = blockIdx.x * 256 + threadIdx.x;      // float4 index, < 196608
    const int c4 = i % (H_ / 4);
    float4 p0 = ((const float4*)g_part)[i];
    float4 p1 = ((const float4*)g_part)[i + 196608];
    float4 p2 = ((const float4*)g_part)[i + 393216];
    float4 bv = ((const float4*)bias)[c4];
    float4 o;
    o.x = tanhf(p0.x + p1.x + p2.x + bv.x);
    o.y = tanhf(p0.y + p1.y + p2.y + bv.y);
    o.z = tanhf(p0.z + p1.z + p2.z + bv.z);
    o.w = tanhf(p0.w + p1.w + p2.w + bv.w);
    ((float4*)g_segproj)[i] = o;
}

// K3a: sdot partials. grid (256/128, 256/64, 4*6) = (2,4,24)
__global__ __launch_bounds__(256) void k_sdot(const int* __restrict__ ind) {
    const int b  = blockIdx.z / 6;
    const int ks = blockIdx.z % 6;
    const int bm = blockIdx.y * 64;
    const int qmax = ind[b * S_ + QPB - 1];
    if (bm > qmax) return;
    const float* P = g_segproj + (size_t)b * NSEG * H_;
    float* Cp = g_spart + ((size_t)(b * 6 + ks)) * (NSEG * NSEG);
    gemm64x128(P, P, Cp, H_, ks * 128, ks * 128 + 128, NSEG,
               bm, blockIdx.x * 128);
}

// K3b: g_sdot = sum of 6 partials (pruned rows only). grid (64, B), block 256
__global__ __launch_bounds__(256) void k_sdot_fix(const int* __restrict__ ind) {
    const int b    = blockIdx.y;
    const int qmax = ind[b * S_ + QPB - 1];
    const int row  = blockIdx.x * 4 + (threadIdx.x >> 6);
    if (row > qmax) return;
    const int c4   = threadIdx.x & 63;
    const size_t e = (size_t)row * 64 + c4;            // float4 idx in [256x256]
    const size_t base = (size_t)b * 6 * (NSEG * NSEG / 4);
    float4 s = make_float4(0.f, 0.f, 0.f, 0.f);
    #pragma unroll
    for (int ks = 0; ks < 6; ks++) {
        float4 p = ((const float4*)g_spart)[base + (size_t)ks * (NSEG * NSEG / 4) + e];
        s.x += p.x; s.y += p.y; s.z += p.z; s.w += p.w;
    }
    ((float4*)(g_sdot + (size_t)b * NSEG * NSEG))[e] = s;
}

// ---------------------------------------------------------------------------
// K4: per query row: masked logsumexp + argmax over 256 segments
// ---------------------------------------------------------------------------
__global__ __launch_bounds__(256) void k_rows(const int* __restrict__ ind,
                                              const int* __restrict__ clc) {
    __shared__ int s_cnt[NSEG];
    __shared__ int s_fst[NSEG];
    const int lane = threadIdx.x & 31;
    const int gw   = blockIdx.x * 8 + (threadIdx.x >> 5);
    const int b    = gw >> 9;
    const int i    = gw & (QPB - 1);

    if (threadIdx.x < NSEG) {
        s_cnt[threadIdx.x] = g_cnt  [b * NSEG + threadIdx.x];
        s_fst[threadIdx.x] = g_first[b * NSEG + threadIdx.x];
    }
    __syncthreads();

    const int q     = ind[b * S_ + i];
    const int label = clc[b * S_ + i];
    const float* srow = g_sdot + ((size_t)b * NSEG + q) * NSEG;

    float s[8]; int c[8];
    #pragma unroll
    for (int t = 0; t < 8; t++) {
        int v = lane + 32 * t;
        s[t] = srow[v];
        c[t] = s_cnt[v];
    }

    float bmax = -INFINITY; int bj = 0x7fffffff;
    #pragma unroll
    for (int t = 0; t < 8; t++) {
        if (c[t] > 0) {
            int j = s_fst[lane + 32 * t];
            if (s[t] > bmax || (s[t] == bmax && j < bj)) { bmax = s[t]; bj = j; }
        }
    }
    #pragma unroll
    for (int off = 16; off; off >>= 1) {
        float os = __shfl_xor_sync(0xffffffffu, bmax, off);
        int   oj = __shfl_xor_sync(0xffffffffu, bj,   off);
        if (os > bmax || (os == bmax && oj < bj)) { bmax = os; bj = oj; }
    }

    float z = 0.0f;
    #pragma unroll
    for (int t = 0; t < 8; t++)
        if (c[t] > 0) z += (float)c[t] * expf(s[t] - bmax);
    #pragma unroll
    for (int off = 16; off; off >>= 1)
        z += __shfl_xor_sync(0xffffffffu, z, off);

    if (lane == 0) {
        int vlab = ind[b * S_ + label];
        float slab = srow[vlab];
        float loss = (logf(z) + bmax) - slab;
        if (label < HALF) loss += 1.0e9f;
        g_loss[gw] = loss;
        g_corr[gw] = (bj == label) ? 1 : 0;
    }
}

// ---------------------------------------------------------------------------
// K5: final reduction -> 6 scalars
// ---------------------------------------------------------------------------
__global__ __launch_bounds__(256) void k_final(float* __restrict__ out) {
    __shared__ double sls[256], slt[256];
    __shared__ int    scs[256], sct[256];
    const int t = threadIdx.x;
    double ls = 0.0, lt = 0.0;
    int cs = 0, ct = 0;
    for (int r = t; r < NROWS; r += 256) {
        if (r & 1) { lt += (double)g_loss[r]; ct += g_corr[r]; }
        else       { ls += (double)g_loss[r]; cs += g_corr[r]; }
    }
    sls[t] = ls; slt[t] = lt; scs[t] = cs; sct[t] = ct;
    __syncthreads();
    for (int off = 128; off; off >>= 1) {
        if (t < off) {
            sls[t] += sls[t + off]; slt[t] += slt[t + off];
            scs[t] += scs[t + off]; sct[t] += sct[t + off];
        }
        __syncthreads();
    }
    if (t == 0) {
        const double n = (double)(NROWS / 2);
        out[0] = (float)(sls[0] / n);
        out[1] = (float)scs[0];
        out[2] = (float)(n + 1e-6);
        out[3] = (float)(slt[0] / n);
        out[4] = (float)sct[0];
        out[5] = (float)(n + 1e-6);
    }
}

// ---------------------------------------------------------------------------
extern "C" void kernel_launch(void* const* d_in, const int* in_sizes, int n_in,
                              void* d_out, int out_size) {
    const float* x    = (const float*)d_in[0];
    const float* W    = (const float*)d_in[1];
    const float* bias = (const float*)d_in[2];
    const int*   ind  = (const int*)  d_in[3];
    const int*   clc  = (const int*)  d_in[4];
    float* out = (float*)d_out;
    (void)in_sizes; (void)n_in; (void)out_size;

    dim3 g1(NSEG, B_);
    k_segsum<<<g1, 192>>>(x, ind);

    dim3 g2(H_ / 128, (B_ * NSEG) / 64, 3);      // (6,16,3) = 288 blocks
    k_proj<<<g2, 256>>>(W);
    k_proj_fix<<<(B_ * NSEG * H_ / 4) / 256, 256>>>(bias);   // 768 blocks

    dim3 g3(NSEG / 128, NSEG / 64, B_ * 6);      // (2,4,24) = 192 blocks
    k_sdot<<<g3, 256>>>(ind);
    dim3 g3f(64, B_);
    k_sdot_fix<<<g3f, 256>>>(ind);

    k_rows<<<NROWS / 8, 256>>>(ind, clc);

    k_final<<<1, 256>>>(out);
}

// round 4
// speedup vs baseline: 1.4268x; 1.0791x over previous
#include <cuda_runtime.h>
#include <math.h>

#define B_    4
#define S_    2048
#define H_    768
#define NSEG  256
#define NROWS 2048
#define QPB   512
#define HALF  1024
#define KSPLIT_P 3
#define KSPLIT_S 12

// -------- scratch --------
__device__ float g_segsum [B_ * NSEG * H_];
__device__ float g_segproj[B_ * NSEG * H_];
__device__ float g_sdot   [B_ * NSEG * NSEG];
__device__ float g_part   [KSPLIT_P * B_ * NSEG * H_];     // proj partials
__device__ float g_spart  [KSPLIT_S * B_ * NSEG * NSEG];   // sdot partials
__device__ int   g_cnt    [B_ * NSEG];
__device__ int   g_first  [B_ * NSEG];
__device__ float g_loss   [NROWS];
__device__ int   g_corr   [NROWS];

typedef unsigned long long u64;

__device__ __forceinline__ void unpack2(u64 v, float& x, float& y) {
    asm("mov.b64 {%0, %1}, %2;" : "=f"(x), "=f"(y) : "l"(v));
}
__device__ __forceinline__ void ffma2(u64& d, u64 a, u64 b) {
    asm("fma.rn.f32x2 %0, %1, %2, %0;" : "+l"(d) : "l"(a), "l"(b));
}

// ---------------------------------------------------------------------------
// K1: segmented sum over sorted indicator + unmasked counts / first-index
// ---------------------------------------------------------------------------
__global__ __launch_bounds__(192) void k_segsum(const float* __restrict__ x,
                                                const int* __restrict__ ind) {
    const int v = blockIdx.x;
    const int b = blockIdx.y;
    const int* row = ind + b * S_;

    int lo, hi;
    { int l = 0, r = S_;
      while (l < r) { int m = (l + r) >> 1; if (row[m] < v) l = m + 1; else r = m; }
      lo = l; }
    { int l = lo, r = S_;
      while (l < r) { int m = (l + r) >> 1; if (row[m] <= v) l = m + 1; else r = m; }
      hi = l; }

    const int t = threadIdx.x;
    float4 acc = make_float4(0.f, 0.f, 0.f, 0.f);
    const float4* xp = (const float4*)(x + ((size_t)b * S_ + lo) * H_) + t;
    for (int i = lo; i < hi; i++) {
        float4 u = *xp; xp += H_ / 4;
        acc.x += u.x; acc.y += u.y; acc.z += u.z; acc.w += u.w;
    }
    ((float4*)(g_segsum + ((size_t)b * NSEG + v) * H_))[t] = acc;

    if (t == 0) {
        int lo2 = lo > HALF ? lo : HALF;
        int c   = hi - lo2; if (c < 0) c = 0;
        g_cnt  [b * NSEG + v] = c;
        g_first[b * NSEG + v] = lo2;
    }
}

// ---------------------------------------------------------------------------
// GEMM tile: Cpart[64 x 128] = A[64 x Kslice] * B[128 x Kslice]^T  (fp32x2)
// 256 threads, 4x8 micro-tile (16 FFMA2 accs), register double-buffered LDG.
// A staged duplicated ((a,a) pairs) so FFMA2 broadcast operands are LDS.128.
// ---------------------------------------------------------------------------
__device__ __forceinline__ void gemm64x128(
    const float* A, const float* Bm, float* Cpart,
    int Ks, int k_begin, int k_end, int ldc, int bm, int bn)
{
    __shared__ __align__(16) float AsD[16][128];
    __shared__ __align__(16) float Bs [16][128];

    const int tid = threadIdx.x;
    const int tx  = tid & 15;
    const int ty  = tid >> 4;
    const int ar  = tid >> 2;
    const int ak  = (tid & 3) << 2;
    const int br  = tid >> 1;
    const int bk  = (tid & 1) << 3;

    const float* Ap = A  + (size_t)(bm + ar) * Ks + ak;
    const float* Bp = Bm + (size_t)(bn + br) * Ks + bk;

    u64 acc[4][4];
    #pragma unroll
    for (int i = 0; i < 4; i++)
        #pragma unroll
        for (int j = 0; j < 4; j++) acc[i][j] = 0ull;

    // prefetch first tile
    float4 ra  = *(const float4*)(Ap + k_begin);
    float4 rb0 = *(const float4*)(Bp + k_begin);
    float4 rb1 = *(const float4*)(Bp + k_begin + 4);

    for (int k0 = k_begin; k0 < k_end; k0 += 16) {
        ((float2*)AsD[ak + 0])[ar] = make_float2(ra.x, ra.x);
        ((float2*)AsD[ak + 1])[ar] = make_float2(ra.y, ra.y);
        ((float2*)AsD[ak + 2])[ar] = make_float2(ra.z, ra.z);
        ((float2*)AsD[ak + 3])[ar] = make_float2(ra.w, ra.w);
        Bs[bk + 0][br] = rb0.x; Bs[bk + 1][br] = rb0.y;
        Bs[bk + 2][br] = rb0.z; Bs[bk + 3][br] = rb0.w;
        Bs[bk + 4][br] = rb1.x; Bs[bk + 5][br] = rb1.y;
        Bs[bk + 6][br] = rb1.z; Bs[bk + 7][br] = rb1.w;
        __syncthreads();

        if (k0 + 16 < k_end) {      // prefetch next tile (hidden under compute)
            ra  = *(const float4*)(Ap + k0 + 16);
            rb0 = *(const float4*)(Bp + k0 + 16);
            rb1 = *(const float4*)(Bp + k0 + 20);
        }

        #pragma unroll
        for (int kk = 0; kk < 16; kk++) {
            ulonglong2 aa0 = *(const ulonglong2*)&AsD[kk][ty << 3];
            ulonglong2 aa1 = *(const ulonglong2*)&AsD[kk][(ty << 3) + 4];
            ulonglong2 bb0 = *(const ulonglong2*)&Bs [kk][tx << 3];
            ulonglong2 bb1 = *(const ulonglong2*)&Bs [kk][(tx << 3) + 4];
            ffma2(acc[0][0], aa0.x, bb0.x); ffma2(acc[0][1], aa0.x, bb0.y);
            ffma2(acc[0][2], aa0.x, bb1.x); ffma2(acc[0][3], aa0.x, bb1.y);
            ffma2(acc[1][0], aa0.y, bb0.x); ffma2(acc[1][1], aa0.y, bb0.y);
            ffma2(acc[1][2], aa0.y, bb1.x); ffma2(acc[1][3], aa0.y, bb1.y);
            ffma2(acc[2][0], aa1.x, bb0.x); ffma2(acc[2][1], aa1.x, bb0.y);
            ffma2(acc[2][2], aa1.x, bb1.x); ffma2(acc[2][3], aa1.x, bb1.y);
            ffma2(acc[3][0], aa1.y, bb0.x); ffma2(acc[3][1], aa1.y, bb0.y);
            ffma2(acc[3][2], aa1.y, bb1.x); ffma2(acc[3][3], aa1.y, bb1.y);
        }
        __syncthreads();
    }

    const int col0 = bn + (tx << 3);
    #pragma unroll
    for (int i = 0; i < 4; i++) {
        float o[8];
        #pragma unroll
        for (int j = 0; j < 4; j++) unpack2(acc[i][j], o[2 * j], o[2 * j + 1]);
        float* cp = Cpart + (size_t)(bm + (ty << 2) + i) * ldc + col0;
        *(float4*)(cp + 0) = make_float4(o[0], o[1], o[2], o[3]);
        *(float4*)(cp + 4) = make_float4(o[4], o[5], o[6], o[7]);
    }
}

// K2a: proj partials. grid (6, 16, 3) = 288 blocks
__global__ __launch_bounds__(256) void k_proj(const float* __restrict__ W) {
    const int ks = blockIdx.z;
    gemm64x128(g_segsum, W, g_part + (size_t)ks * (B_ * NSEG * H_),
               H_, ks * 256, ks * 256 + 256, H_,
               blockIdx.y * 64, blockIdx.x * 128);
}

// K2b: segproj = tanh(sum of 3 partials + bias)
__global__ __launch_bounds__(256) void k_proj_fix(const float* __restrict__ bias) {
    const int i = blockIdx.x * 256 + threadIdx.x;
    const int c4 = i % (H_ / 4);
    float4 p0 = ((const float4*)g_part)[i];
    float4 p1 = ((const float4*)g_part)[i + 196608];
    float4 p2 = ((const float4*)g_part)[i + 393216];
    float4 bv = ((const float4*)bias)[c4];
    float4 o;
    o.x = tanhf(p0.x + p1.x + p2.x + bv.x);
    o.y = tanhf(p0.y + p1.y + p2.y + bv.y);
    o.z = tanhf(p0.z + p1.z + p2.z + bv.z);
    o.w = tanhf(p0.w + p1.w + p2.w + bv.w);
    ((float4*)g_segproj)[i] = o;
}

// K3a: sdot partials, split-K 12. grid (2, 4, 48)
__global__ __launch_bounds__(256) void k_sdot(const int* __restrict__ ind) {
    const int b  = blockIdx.z / KSPLIT_S;
    const int ks = blockIdx.z % KSPLIT_S;
    const int bm = blockIdx.y * 64;
    const int qmax = ind[b * S_ + QPB - 1];
    if (bm > qmax) return;
    const float* P = g_segproj + (size_t)b * NSEG * H_;
    float* Cp = g_spart + ((size_t)(b * KSPLIT_S + ks)) * (NSEG * NSEG);
    gemm64x128(P, P, Cp, H_, ks * 64, ks * 64 + 64, NSEG,
               bm, blockIdx.x * 128);
}

// K3b: g_sdot = sum of 12 partials (pruned rows). grid (64, B), block 256
__global__ __launch_bounds__(256) void k_sdot_fix(const int* __restrict__ ind) {
    const int b    = blockIdx.y;
    const int qmax = ind[b * S_ + QPB - 1];
    const int row  = blockIdx.x * 4 + (threadIdx.x >> 6);
    if (row > qmax) return;
    const int c4   = threadIdx.x & 63;
    const size_t e = (size_t)row * 64 + c4;
    const size_t base = (size_t)b * KSPLIT_S * (NSEG * NSEG / 4);
    float4 s = make_float4(0.f, 0.f, 0.f, 0.f);
    #pragma unroll
    for (int ks = 0; ks < KSPLIT_S; ks++) {
        float4 p = ((const float4*)g_spart)[base + (size_t)ks * (NSEG * NSEG / 4) + e];
        s.x += p.x; s.y += p.y; s.z += p.z; s.w += p.w;
    }
    ((float4*)(g_sdot + (size_t)b * NSEG * NSEG))[e] = s;
}

// ---------------------------------------------------------------------------
// K4: per query row: masked logsumexp + argmax over 256 segments
// ---------------------------------------------------------------------------
__global__ __launch_bounds__(256) void k_rows(const int* __restrict__ ind,
                                              const int* __restrict__ clc) {
    __shared__ int s_cnt[NSEG];
    __shared__ int s_fst[NSEG];
    const int lane = threadIdx.x & 31;
    const int gw   = blockIdx.x * 8 + (threadIdx.x >> 5);
    const int b    = gw >> 9;
    const int i    = gw & (QPB - 1);

    if (threadIdx.x < NSEG) {
        s_cnt[threadIdx.x] = g_cnt  [b * NSEG + threadIdx.x];
        s_fst[threadIdx.x] = g_first[b * NSEG + threadIdx.x];
    }
    __syncthreads();

    const int q     = ind[b * S_ + i];
    const int label = clc[b * S_ + i];
    const float* srow = g_sdot + ((size_t)b * NSEG + q) * NSEG;

    float s[8]; int c[8];
    #pragma unroll
    for (int t = 0; t < 8; t++) {
        int v = lane + 32 * t;
        s[t] = srow[v];
        c[t] = s_cnt[v];
    }

    float bmax = -INFINITY; int bj = 0x7fffffff;
    #pragma unroll
    for (int t = 0; t < 8; t++) {
        if (c[t] > 0) {
            int j = s_fst[lane + 32 * t];
            if (s[t] > bmax || (s[t] == bmax && j < bj)) { bmax = s[t]; bj = j; }
        }
    }
    #pragma unroll
    for (int off = 16; off; off >>= 1) {
        float os = __shfl_xor_sync(0xffffffffu, bmax, off);
        int   oj = __shfl_xor_sync(0xffffffffu, bj,   off);
        if (os > bmax || (os == bmax && oj < bj)) { bmax = os; bj = oj; }
    }

    float z = 0.0f;
    #pragma unroll
    for (int t = 0; t < 8; t++)
        if (c[t] > 0) z += (float)c[t] * expf(s[t] - bmax);
    #pragma unroll
    for (int off = 16; off; off >>= 1)
        z += __shfl_xor_sync(0xffffffffu, z, off);

    if (lane == 0) {
        int vlab = ind[b * S_ + label];
        float slab = srow[vlab];
        float loss = (logf(z) + bmax) - slab;
        if (label < HALF) loss += 1.0e9f;
        g_loss[gw] = loss;
        g_corr[gw] = (bj == label) ? 1 : 0;
    }
}

// ---------------------------------------------------------------------------
// K5: final reduction -> 6 scalars
// ---------------------------------------------------------------------------
__global__ __launch_bounds__(256) void k_final(float* __restrict__ out) {
    __shared__ double sls[256], slt[256];
    __shared__ int    scs[256], sct[256];
    const int t = threadIdx.x;
    double ls = 0.0, lt = 0.0;
    int cs = 0, ct = 0;
    for (int r = t; r < NROWS; r += 256) {
        if (r & 1) { lt += (double)g_loss[r]; ct += g_corr[r]; }
        else       { ls += (double)g_loss[r]; cs += g_corr[r]; }
    }
    sls[t] = ls; slt[t] = lt; scs[t] = cs; sct[t] = ct;
    __syncthreads();
    for (int off = 128; off; off >>= 1) {
        if (t < off) {
            sls[t] += sls[t + off]; slt[t] += slt[t + off];
            scs[t] += scs[t + off]; sct[t] += sct[t + off];
        }
        __syncthreads();
    }
    if (t == 0) {
        const double n = (double)(NROWS / 2);
        out[0] = (float)(sls[0] / n);
        out[1] = (float)scs[0];
        out[2] = (float)(n + 1e-6);
        out[3] = (float)(slt[0] / n);
        out[4] = (float)sct[0];
        out[5] = (float)(n + 1e-6);
    }
}

// ---------------------------------------------------------------------------
extern "C" void kernel_launch(void* const* d_in, const int* in_sizes, int n_in,
                              void* d_out, int out_size) {
    const float* x    = (const float*)d_in[0];
    const float* W    = (const float*)d_in[1];
    const float* bias = (const float*)d_in[2];
    const int*   ind  = (const int*)  d_in[3];
    const int*   clc  = (const int*)  d_in[4];
    float* out = (float*)d_out;
    (void)in_sizes; (void)n_in; (void)out_size;

    dim3 g1(NSEG, B_);
    k_segsum<<<g1, 192>>>(x, ind);

    dim3 g2(H_ / 128, (B_ * NSEG) / 64, KSPLIT_P);   // 288 blocks
    k_proj<<<g2, 256>>>(W);
    k_proj_fix<<<(B_ * NSEG * H_ / 4) / 256, 256>>>(bias);

    dim3 g3(NSEG / 128, NSEG / 64, B_ * KSPLIT_S);   // (2,4,48)
    k_sdot<<<g3, 256>>>(ind);
    dim3 g3f(64, B_);
    k_sdot_fix<<<g3f, 256>>>(ind);

    k_rows<<<NROWS / 8, 256>>>(ind, clc);

    k_final<<<1, 256>>>(out);
}

// round 5
// speedup vs baseline: 1.4272x; 1.0003x over previous
#include <cuda_runtime.h>
#include <math.h>

#define B_    4
#define S_    2048
#define H_    768
#define NSEG  256
#define NROWS 2048
#define QPB   512
#define HALF  1024
#define KSPLIT_P 3
#define KSPLIT_S 12

// -------- scratch --------
__device__ float g_segsum [B_ * NSEG * H_];
__device__ float g_segproj[B_ * NSEG * H_];
__device__ float g_sdot   [B_ * NSEG * NSEG];
__device__ float g_part   [KSPLIT_P * B_ * NSEG * H_];
__device__ float g_spart  [KSPLIT_S * B_ * NSEG * NSEG];
__device__ int   g_cnt    [B_ * NSEG];
__device__ int   g_first  [B_ * NSEG];
__device__ float g_loss   [NROWS];
__device__ int   g_corr   [NROWS];

typedef unsigned long long u64;

__device__ __forceinline__ void unpack2(u64 v, float& x, float& y) {
    asm("mov.b64 {%0, %1}, %2;" : "=f"(x), "=f"(y) : "l"(v));
}
__device__ __forceinline__ void ffma2(u64& d, u64 a, u64 b) {
    asm("fma.rn.f32x2 %0, %1, %2, %0;" : "+l"(d) : "l"(a), "l"(b));
}

// ---------------------------------------------------------------------------
// K1: segmented sum, MLP-4 batched loads (sequential adds keep fp32 order)
// ---------------------------------------------------------------------------
__global__ __launch_bounds__(192) void k_segsum(const float* __restrict__ x,
                                                const int* __restrict__ ind) {
    const int v = blockIdx.x;
    const int b = blockIdx.y;
    const int* row = ind + b * S_;

    int lo, hi;
    { int l = 0, r = S_;
      while (l < r) { int m = (l + r) >> 1; if (row[m] < v) l = m + 1; else r = m; }
      lo = l; }
    { int l = lo, r = S_;
      while (l < r) { int m = (l + r) >> 1; if (row[m] <= v) l = m + 1; else r = m; }
      hi = l; }

    const int t = threadIdx.x;
    const int H4 = H_ / 4;
    float4 acc = make_float4(0.f, 0.f, 0.f, 0.f);
    const float4* xp = (const float4*)(x + ((size_t)b * S_ + lo) * H_) + t;

    int i = lo;
    for (; i + 4 <= hi; i += 4) {
        float4 u0 = xp[0];
        float4 u1 = xp[H4];
        float4 u2 = xp[2 * H4];
        float4 u3 = xp[3 * H4];
        xp += 4 * H4;
        acc.x += u0.x; acc.y += u0.y; acc.z += u0.z; acc.w += u0.w;
        acc.x += u1.x; acc.y += u1.y; acc.z += u1.z; acc.w += u1.w;
        acc.x += u2.x; acc.y += u2.y; acc.z += u2.z; acc.w += u2.w;
        acc.x += u3.x; acc.y += u3.y; acc.z += u3.z; acc.w += u3.w;
    }
    for (; i < hi; i++) {
        float4 u = *xp; xp += H4;
        acc.x += u.x; acc.y += u.y; acc.z += u.z; acc.w += u.w;
    }
    ((float4*)(g_segsum + ((size_t)b * NSEG + v) * H_))[t] = acc;

    if (t == 0) {
        int lo2 = lo > HALF ? lo : HALF;
        int c   = hi - lo2; if (c < 0) c = 0;
        g_cnt  [b * NSEG + v] = c;
        g_first[b * NSEG + v] = lo2;
    }
}

// ---------------------------------------------------------------------------
// GEMM tile: Cpart[64 x 128] = A[64 x Kslice] * B[128 x Kslice]^T  (fp32x2)
// Double-buffered smem: ONE __syncthreads per k-tile.
// ---------------------------------------------------------------------------
__device__ __forceinline__ void gemm64x128(
    const float* A, const float* Bm, float* Cpart,
    int Ks, int k_begin, int k_end, int ldc, int bm, int bn)
{
    __shared__ __align__(16) float AsD[2][16][128];
    __shared__ __align__(16) float Bs [2][16][128];

    const int tid = threadIdx.x;
    const int tx  = tid & 15;
    const int ty  = tid >> 4;
    const int ar  = tid >> 2;
    const int ak  = (tid & 3) << 2;
    const int br  = tid >> 1;
    const int bk  = (tid & 1) << 3;

    const float* Ap = A  + (size_t)(bm + ar) * Ks + ak;
    const float* Bp = Bm + (size_t)(bn + br) * Ks + bk;

    u64 acc[4][4];
    #pragma unroll
    for (int i = 0; i < 4; i++)
        #pragma unroll
        for (int j = 0; j < 4; j++) acc[i][j] = 0ull;

    // load tile0 -> regs, store to buf0
    float4 ra  = *(const float4*)(Ap + k_begin);
    float4 rb0 = *(const float4*)(Bp + k_begin);
    float4 rb1 = *(const float4*)(Bp + k_begin + 4);
    ((float2*)AsD[0][ak + 0])[ar] = make_float2(ra.x, ra.x);
    ((float2*)AsD[0][ak + 1])[ar] = make_float2(ra.y, ra.y);
    ((float2*)AsD[0][ak + 2])[ar] = make_float2(ra.z, ra.z);
    ((float2*)AsD[0][ak + 3])[ar] = make_float2(ra.w, ra.w);
    Bs[0][bk + 0][br] = rb0.x; Bs[0][bk + 1][br] = rb0.y;
    Bs[0][bk + 2][br] = rb0.z; Bs[0][bk + 3][br] = rb0.w;
    Bs[0][bk + 4][br] = rb1.x; Bs[0][bk + 5][br] = rb1.y;
    Bs[0][bk + 6][br] = rb1.z; Bs[0][bk + 7][br] = rb1.w;
    __syncthreads();

    // prefetch tile1 -> regs
    if (k_begin + 16 < k_end) {
        ra  = *(const float4*)(Ap + k_begin + 16);
        rb0 = *(const float4*)(Bp + k_begin + 16);
        rb1 = *(const float4*)(Bp + k_begin + 20);
    }

    int p = 0;
    for (int k0 = k_begin; k0 < k_end; k0 += 16) {
        // stage tile k0+16 into the other buffer (regs already hold it)
        if (k0 + 16 < k_end) {
            const int q = p ^ 1;
            ((float2*)AsD[q][ak + 0])[ar] = make_float2(ra.x, ra.x);
            ((float2*)AsD[q][ak + 1])[ar] = make_float2(ra.y, ra.y);
            ((float2*)AsD[q][ak + 2])[ar] = make_float2(ra.z, ra.z);
            ((float2*)AsD[q][ak + 3])[ar] = make_float2(ra.w, ra.w);
            Bs[q][bk + 0][br] = rb0.x; Bs[q][bk + 1][br] = rb0.y;
            Bs[q][bk + 2][br] = rb0.z; Bs[q][bk + 3][br] = rb0.w;
            Bs[q][bk + 4][br] = rb1.x; Bs[q][bk + 5][br] = rb1.y;
            Bs[q][bk + 6][br] = rb1.z; Bs[q][bk + 7][br] = rb1.w;
        }
        // prefetch tile k0+32 -> regs (hidden under compute)
        if (k0 + 32 < k_end) {
            ra  = *(const float4*)(Ap + k0 + 32);
            rb0 = *(const float4*)(Bp + k0 + 32);
            rb1 = *(const float4*)(Bp + k0 + 36);
        }
        // compute from buffer p
        #pragma unroll
        for (int kk = 0; kk < 16; kk++) {
            ulonglong2 aa0 = *(const ulonglong2*)&AsD[p][kk][ty << 3];
            ulonglong2 aa1 = *(const ulonglong2*)&AsD[p][kk][(ty << 3) + 4];
            ulonglong2 bb0 = *(const ulonglong2*)&Bs [p][kk][tx << 3];
            ulonglong2 bb1 = *(const ulonglong2*)&Bs [p][kk][(tx << 3) + 4];
            ffma2(acc[0][0], aa0.x, bb0.x); ffma2(acc[0][1], aa0.x, bb0.y);
            ffma2(acc[0][2], aa0.x, bb1.x); ffma2(acc[0][3], aa0.x, bb1.y);
            ffma2(acc[1][0], aa0.y, bb0.x); ffma2(acc[1][1], aa0.y, bb0.y);
            ffma2(acc[1][2], aa0.y, bb1.x); ffma2(acc[1][3], aa0.y, bb1.y);
            ffma2(acc[2][0], aa1.x, bb0.x); ffma2(acc[2][1], aa1.x, bb0.y);
            ffma2(acc[2][2], aa1.x, bb1.x); ffma2(acc[2][3], aa1.x, bb1.y);
            ffma2(acc[3][0], aa1.y, bb0.x); ffma2(acc[3][1], aa1.y, bb0.y);
            ffma2(acc[3][2], aa1.y, bb1.x); ffma2(acc[3][3], aa1.y, bb1.y);
        }
        __syncthreads();
        p ^= 1;
    }

    const int col0 = bn + (tx << 3);
    #pragma unroll
    for (int i = 0; i < 4; i++) {
        float o[8];
        #pragma unroll
        for (int j = 0; j < 4; j++) unpack2(acc[i][j], o[2 * j], o[2 * j + 1]);
        float* cp = Cpart + (size_t)(bm + (ty << 2) + i) * ldc + col0;
        *(float4*)(cp + 0) = make_float4(o[0], o[1], o[2], o[3]);
        *(float4*)(cp + 4) = make_float4(o[4], o[5], o[6], o[7]);
    }
}

// K2a: proj partials. grid (6, 16, 3) = 288 blocks
__global__ __launch_bounds__(256) void k_proj(const float* __restrict__ W) {
    const int ks = blockIdx.z;
    gemm64x128(g_segsum, W, g_part + (size_t)ks * (B_ * NSEG * H_),
               H_, ks * 256, ks * 256 + 256, H_,
               blockIdx.y * 64, blockIdx.x * 128);
}

// K2b: segproj = tanh(sum of 3 partials + bias)
__global__ __launch_bounds__(256) void k_proj_fix(const float* __restrict__ bias) {
    const int i = blockIdx.x * 256 + threadIdx.x;
    const int c4 = i % (H_ / 4);
    float4 p0 = ((const float4*)g_part)[i];
    float4 p1 = ((const float4*)g_part)[i + 196608];
    float4 p2 = ((const float4*)g_part)[i + 393216];
    float4 bv = ((const float4*)bias)[c4];
    float4 o;
    o.x = tanhf(p0.x + p1.x + p2.x + bv.x);
    o.y = tanhf(p0.y + p1.y + p2.y + bv.y);
    o.z = tanhf(p0.z + p1.z + p2.z + bv.z);
    o.w = tanhf(p0.w + p1.w + p2.w + bv.w);
    ((float4*)g_segproj)[i] = o;
}

// K3a: sdot partials, split-K 12. grid (2, 4, 48)
__global__ __launch_bounds__(256) void k_sdot(const int* __restrict__ ind) {
    const int b  = blockIdx.z / KSPLIT_S;
    const int ks = blockIdx.z % KSPLIT_S;
    const int bm = blockIdx.y * 64;
    const int qmax = ind[b * S_ + QPB - 1];
    if (bm > qmax) return;
    const float* P = g_segproj + (size_t)b * NSEG * H_;
    float* Cp = g_spart + ((size_t)(b * KSPLIT_S + ks)) * (NSEG * NSEG);
    gemm64x128(P, P, Cp, H_, ks * 64, ks * 64 + 64, NSEG,
               bm, blockIdx.x * 128);
}

// K3b: g_sdot = sum of 12 partials (pruned rows). grid (64, B)
__global__ __launch_bounds__(256) void k_sdot_fix(const int* __restrict__ ind) {
    const int b    = blockIdx.y;
    const int qmax = ind[b * S_ + QPB - 1];
    const int row  = blockIdx.x * 4 + (threadIdx.x >> 6);
    if (row > qmax) return;
    const int c4   = threadIdx.x & 63;
    const size_t e = (size_t)row * 64 + c4;
    const size_t base = (size_t)b * KSPLIT_S * (NSEG * NSEG / 4);
    float4 s = make_float4(0.f, 0.f, 0.f, 0.f);
    #pragma unroll
    for (int ks = 0; ks < KSPLIT_S; ks++) {
        float4 p = ((const float4*)g_spart)[base + (size_t)ks * (NSEG * NSEG / 4) + e];
        s.x += p.x; s.y += p.y; s.z += p.z; s.w += p.w;
    }
    ((float4*)(g_sdot + (size_t)b * NSEG * NSEG))[e] = s;
}

// ---------------------------------------------------------------------------
// K4: per query row: masked logsumexp + argmax over 256 segments
// ---------------------------------------------------------------------------
__global__ __launch_bounds__(256) void k_rows(const int* __restrict__ ind,
                                              const int* __restrict__ clc) {
    __shared__ int s_cnt[NSEG];
    __shared__ int s_fst[NSEG];
    const int lane = threadIdx.x & 31;
    const int gw   = blockIdx.x * 8 + (threadIdx.x >> 5);
    const int b    = gw >> 9;
    const int i    = gw & (QPB - 1);

    if (threadIdx.x < NSEG) {
        s_cnt[threadIdx.x] = g_cnt  [b * NSEG + threadIdx.x];
        s_fst[threadIdx.x] = g_first[b * NSEG + threadIdx.x];
    }
    __syncthreads();

    const int q     = ind[b * S_ + i];
    const int label = clc[b * S_ + i];
    const float* srow = g_sdot + ((size_t)b * NSEG + q) * NSEG;

    float s[8]; int c[8];
    #pragma unroll
    for (int t = 0; t < 8; t++) {
        int v = lane + 32 * t;
        s[t] = __ldg(srow + v);
        c[t] = s_cnt[v];
    }

    float bmax = -INFINITY; int bj = 0x7fffffff;
    #pragma unroll
    for (int t = 0; t < 8; t++) {
        if (c[t] > 0) {
            int j = s_fst[lane + 32 * t];
            if (s[t] > bmax || (s[t] == bmax && j < bj)) { bmax = s[t]; bj = j; }
        }
    }
    #pragma unroll
    for (int off = 16; off; off >>= 1) {
        float os = __shfl_xor_sync(0xffffffffu, bmax, off);
        int   oj = __shfl_xor_sync(0xffffffffu, bj,   off);
        if (os > bmax || (os == bmax && oj < bj)) { bmax = os; bj = oj; }
    }

    float z = 0.0f;
    #pragma unroll
    for (int t = 0; t < 8; t++)
        if (c[t] > 0) z += (float)c[t] * expf(s[t] - bmax);
    #pragma unroll
    for (int off = 16; off; off >>= 1)
        z += __shfl_xor_sync(0xffffffffu, z, off);

    if (lane == 0) {
        int vlab = ind[b * S_ + label];
        float slab = __ldg(srow + vlab);
        float loss = (logf(z) + bmax) - slab;
        if (label < HALF) loss += 1.0e9f;
        g_loss[gw] = loss;
        g_corr[gw] = (bj == label) ? 1 : 0;
    }
}

// ---------------------------------------------------------------------------
// K5: final reduction -> 6 scalars
// ---------------------------------------------------------------------------
__global__ __launch_bounds__(256) void k_final(float* __restrict__ out) {
    __shared__ double sls[256], slt[256];
    __shared__ int    scs[256], sct[256];
    const int t = threadIdx.x;
    double ls = 0.0, lt = 0.0;
    int cs = 0, ct = 0;
    for (int r = t; r < NROWS; r += 256) {
        if (r & 1) { lt += (double)g_loss[r]; ct += g_corr[r]; }
        else       { ls += (double)g_loss[r]; cs += g_corr[r]; }
    }
    sls[t] = ls; slt[t] = lt; scs[t] = cs; sct[t] = ct;
    __syncthreads();
    for (int off = 128; off; off >>= 1) {
        if (t < off) {
            sls[t] += sls[t + off]; slt[t] += slt[t + off];
            scs[t] += scs[t + off]; sct[t] += sct[t + off];
        }
        __syncthreads();
    }
    if (t == 0) {
        const double n = (double)(NROWS / 2);
        out[0] = (float)(sls[0] / n);
        out[1] = (float)scs[0];
        out[2] = (float)(n + 1e-6);
        out[3] = (float)(slt[0] / n);
        out[4] = (float)sct[0];
        out[5] = (float)(n + 1e-6);
    }
}

// ---------------------------------------------------------------------------
extern "C" void kernel_launch(void* const* d_in, const int* in_sizes, int n_in,
                              void* d_out, int out_size) {
    const float* x    = (const float*)d_in[0];
    const float* W    = (const float*)d_in[1];
    const float* bias = (const float*)d_in[2];
    const int*   ind  = (const int*)  d_in[3];
    const int*   clc  = (const int*)  d_in[4];
    float* out = (float*)d_out;
    (void)in_sizes; (void)n_in; (void)out_size;

    dim3 g1(NSEG, B_);
    k_segsum<<<g1, 192>>>(x, ind);

    dim3 g2(H_ / 128, (B_ * NSEG) / 64, KSPLIT_P);
    k_proj<<<g2, 256>>>(W);
    k_proj_fix<<<(B_ * NSEG * H_ / 4) / 256, 256>>>(bias);

    dim3 g3(NSEG / 128, NSEG / 64, B_ * KSPLIT_S);
    k_sdot<<<g3, 256>>>(ind);
    dim3 g3f(64, B_);
    k_sdot_fix<<<g3f, 256>>>(ind);

    k_rows<<<NROWS / 8, 256>>>(ind, clc);

    k_final<<<1, 256>>>(out);
}

// round 7
// speedup vs baseline: 2.1657x; 1.5174x over previous
#include <cuda_runtime.h>
#include <cuda_bf16.h>
#include <math.h>
#include <stdint.h>

#define B_    4
#define S_    2048
#define H_    768
#define NSEG  256
#define NROWS 2048
#define QPB   512
#define HALF  1024
#define KS_P  3            // proj split-K (256 cols each)
#define KS_S  6            // sdot split-K (128 cols each)

#define SROW  24           // smem row stride in bf16 (16 data + 8 pad = 48B)
#define SLABE (128 * SROW) // elements per 128x16 slab
#define SMEM_MMA (2 * 6 * SLABE * 2)   // 2 stages x (3A + 3B) slabs x bf16 = 73728 B

// -------- scratch (device globals; no allocation allowed) --------
__device__ __nv_bfloat16 g_A0[B_ * NSEG * H_];
__device__ __nv_bfloat16 g_A1[B_ * NSEG * H_];
__device__ __nv_bfloat16 g_A2[B_ * NSEG * H_];
__device__ __nv_bfloat16 g_W0[H_ * H_];
__device__ __nv_bfloat16 g_W1[H_ * H_];
__device__ __nv_bfloat16 g_W2[H_ * H_];
__device__ __nv_bfloat16 g_P0[B_ * NSEG * H_];
__device__ __nv_bfloat16 g_P1[B_ * NSEG * H_];
__device__ __nv_bfloat16 g_P2[B_ * NSEG * H_];
__device__ float g_part [KS_P * B_ * NSEG * H_];
__device__ float g_spart[KS_S * B_ * NSEG * NSEG];
__device__ float g_sdot [B_ * NSEG * NSEG];
__device__ int   g_cnt  [B_ * NSEG];
__device__ int   g_first[B_ * NSEG];
__device__ float g_loss [NROWS];
__device__ int   g_corr [NROWS];

// bf16 3-way split (residuals exact in fp32)
__device__ __forceinline__ void split3(float x, __nv_bfloat16& b0,
                                       __nv_bfloat16& b1, __nv_bfloat16& b2) {
    b0 = __float2bfloat16(x);
    float r = x - __bfloat162float(b0);
    b1 = __float2bfloat16(r);
    float r2 = r - __bfloat162float(b1);
    b2 = __float2bfloat16(r2);
}

union Pack4 { __nv_bfloat16 h[4]; unsigned long long u; };

// mma.sync m16n8k16 row.col f32.bf16.bf16.f32 (sm_80+, valid on compute_103)
__device__ __forceinline__ void mma16816(float* c,
                                         uint32_t a0, uint32_t a1, uint32_t a2, uint32_t a3,
                                         uint32_t b0, uint32_t b1) {
    asm volatile(
        "mma.sync.aligned.m16n8k16.row.col.f32.bf16.bf16.f32 "
        "{%0,%1,%2,%3}, {%4,%5,%6,%7}, {%8,%9}, {%0,%1,%2,%3};"
        : "+f"(c[0]), "+f"(c[1]), "+f"(c[2]), "+f"(c[3])
        : "r"(a0), "r"(a1), "r"(a2), "r"(a3), "r"(b0), "r"(b1));
}

// ---------------------------------------------------------------------------
// K1: segmented sum over sorted indicator -> bf16x3 splits + cnt/first
// ---------------------------------------------------------------------------
__global__ __launch_bounds__(192) void k_segsum(const float* __restrict__ x,
                                                const int* __restrict__ ind) {
    const int v = blockIdx.x;
    const int b = blockIdx.y;
    const int* row = ind + b * S_;

    int lo, hi;
    { int l = 0, r = S_;
      while (l < r) { int m = (l + r) >> 1; if (row[m] < v) l = m + 1; else r = m; }
      lo = l; }
    { int l = lo, r = S_;
      while (l < r) { int m = (l + r) >> 1; if (row[m] <= v) l = m + 1; else r = m; }
      hi = l; }

    const int t = threadIdx.x;
    const int H4 = H_ / 4;
    float4 acc = make_float4(0.f, 0.f, 0.f, 0.f);
    const float4* xp = (const float4*)(x + ((size_t)b * S_ + lo) * H_) + t;

    int i = lo;
    for (; i + 4 <= hi; i += 4) {
        float4 u0 = xp[0]; float4 u1 = xp[H4];
        float4 u2 = xp[2 * H4]; float4 u3 = xp[3 * H4];
        xp += 4 * H4;
        acc.x += u0.x; acc.y += u0.y; acc.z += u0.z; acc.w += u0.w;
        acc.x += u1.x; acc.y += u1.y; acc.z += u1.z; acc.w += u1.w;
        acc.x += u2.x; acc.y += u2.y; acc.z += u2.z; acc.w += u2.w;
        acc.x += u3.x; acc.y += u3.y; acc.z += u3.z; acc.w += u3.w;
    }
    for (; i < hi; i++) {
        float4 u = *xp; xp += H4;
        acc.x += u.x; acc.y += u.y; acc.z += u.z; acc.w += u.w;
    }

    Pack4 p0, p1, p2;
    float a[4] = {acc.x, acc.y, acc.z, acc.w};
    #pragma unroll
    for (int j = 0; j < 4; j++) split3(a[j], p0.h[j], p1.h[j], p2.h[j]);
    const size_t e = ((size_t)b * NSEG + v) * H_ + t * 4;
    *(unsigned long long*)(g_A0 + e) = p0.u;
    *(unsigned long long*)(g_A1 + e) = p1.u;
    *(unsigned long long*)(g_A2 + e) = p2.u;

    if (t == 0) {
        int lo2 = lo > HALF ? lo : HALF;
        int c   = hi - lo2; if (c < 0) c = 0;
        g_cnt  [b * NSEG + v] = c;
        g_first[b * NSEG + v] = lo2;
    }
}

// ---------------------------------------------------------------------------
// K1b: W -> bf16x3 splits
// ---------------------------------------------------------------------------
__global__ __launch_bounds__(256) void k_convW(const float* __restrict__ W) {
    const int i = blockIdx.x * 256 + threadIdx.x;     // float4 idx < 147456
    float4 w = ((const float4*)W)[i];
    Pack4 p0, p1, p2;
    float a[4] = {w.x, w.y, w.z, w.w};
    #pragma unroll
    for (int j = 0; j < 4; j++) split3(a[j], p0.h[j], p1.h[j], p2.h[j]);
    *(unsigned long long*)(g_W0 + (size_t)i * 4) = p0.u;
    *(unsigned long long*)(g_W1 + (size_t)i * 4) = p1.u;
    *(unsigned long long*)(g_W2 + (size_t)i * 4) = p2.u;
}

// ---------------------------------------------------------------------------
// mma GEMM: Cpart[128x128] = sum_{sa+sb<=2} Asa[128xK] @ Bsb[128xK]^T
// 256 threads / 8 warps (2x4), warp tile 64x32, double-buffered smem.
// ---------------------------------------------------------------------------
__device__ __forceinline__ void gemm_mma(
    const __nv_bfloat16* A0g, const __nv_bfloat16* A1g, const __nv_bfloat16* A2g,
    const __nv_bfloat16* B0g, const __nv_bfloat16* B1g, const __nv_bfloat16* B2g,
    float* Cout, int ldc, int bm, int bn, int kb, int ke, __nv_bfloat16* sm)
{
    const int tid  = threadIdx.x;
    const int wid  = tid >> 5, lane = tid & 31;
    const int wm   = wid & 1, wn = wid >> 1;
    const int gid  = lane >> 2, tid4 = lane & 3;
    const int lrow = tid >> 1;            // 0..127 (global-load coalescing)
    const int lhalf = (tid & 1) * 8;      // k element offset (8 bf16 = 16B)

    const __nv_bfloat16* Ag[3] = {A0g, A1g, A2g};
    const __nv_bfloat16* Bg[3] = {B0g, B1g, B2g};

    float acc[4][4][4];
    #pragma unroll
    for (int i = 0; i < 4; i++)
        #pragma unroll
        for (int j = 0; j < 4; j++)
            #pragma unroll
            for (int k = 0; k < 4; k++) acc[i][j][k] = 0.f;

    // prefetch tile 0 into regs
    uint4 ra[3], rb[3];
    #pragma unroll
    for (int s = 0; s < 3; s++) {
        ra[s] = *(const uint4*)(Ag[s] + (size_t)(bm + lrow) * H_ + kb + lhalf);
        rb[s] = *(const uint4*)(Bg[s] + (size_t)(bn + lrow) * H_ + kb + lhalf);
    }

    int stage = 0;
    for (int k0 = kb; k0 < ke; k0 += 16) {
        __nv_bfloat16* base = sm + stage * 6 * SLABE;
        #pragma unroll
        for (int s = 0; s < 3; s++) {
            *(uint4*)(base + s * SLABE + lrow * SROW + lhalf)       = ra[s];
            *(uint4*)(base + (3 + s) * SLABE + lrow * SROW + lhalf) = rb[s];
        }
        __syncthreads();

        if (k0 + 16 < ke) {
            #pragma unroll
            for (int s = 0; s < 3; s++) {
                ra[s] = *(const uint4*)(Ag[s] + (size_t)(bm + lrow) * H_ + k0 + 16 + lhalf);
                rb[s] = *(const uint4*)(Bg[s] + (size_t)(bn + lrow) * H_ + k0 + 16 + lhalf);
            }
        }

        #pragma unroll
        for (int sa = 0; sa < 3; sa++) {
            const __nv_bfloat16* As_ = base + sa * SLABE;
            uint32_t af[4][4];
            #pragma unroll
            for (int mi = 0; mi < 4; mi++) {
                int r0 = wm * 64 + mi * 16;
                af[mi][0] = *(const uint32_t*)(As_ + (r0 + gid)     * SROW + tid4 * 2);
                af[mi][1] = *(const uint32_t*)(As_ + (r0 + gid + 8) * SROW + tid4 * 2);
                af[mi][2] = *(const uint32_t*)(As_ + (r0 + gid)     * SROW + tid4 * 2 + 8);
                af[mi][3] = *(const uint32_t*)(As_ + (r0 + gid + 8) * SROW + tid4 * 2 + 8);
            }
            #pragma unroll
            for (int sb = 0; sb < 3; sb++) {
                if (sa + sb > 2) continue;      // 6 cross terms total
                const __nv_bfloat16* Bs_ = base + (3 + sb) * SLABE;
                #pragma unroll
                for (int ni = 0; ni < 4; ni++) {
                    int n0 = wn * 32 + ni * 8;
                    uint32_t b0 = *(const uint32_t*)(Bs_ + (n0 + gid) * SROW + tid4 * 2);
                    uint32_t b1 = *(const uint32_t*)(Bs_ + (n0 + gid) * SROW + tid4 * 2 + 8);
                    #pragma unroll
                    for (int mi = 0; mi < 4; mi++)
                        mma16816(acc[mi][ni], af[mi][0], af[mi][1], af[mi][2], af[mi][3], b0, b1);
                }
            }
        }
        __syncthreads();
        stage ^= 1;
    }

    // store fp32 partial tile
    #pragma unroll
    for (int mi = 0; mi < 4; mi++) {
        int r0 = bm + wm * 64 + mi * 16 + gid;
        #pragma unroll
        for (int ni = 0; ni < 4; ni++) {
            int c = bn + wn * 32 + ni * 8 + tid4 * 2;
            *(float2*)(Cout + (size_t)r0 * ldc + c)       = make_float2(acc[mi][ni][0], acc[mi][ni][1]);
            *(float2*)(Cout + (size_t)(r0 + 8) * ldc + c) = make_float2(acc[mi][ni][2], acc[mi][ni][3]);
        }
    }
}

// K2a: proj partials. grid (6, 8, KS_P) = 144 blocks
__global__ __launch_bounds__(256) void k_proj_mma() {
    extern __shared__ __align__(16) __nv_bfloat16 sm[];
    const int ks = blockIdx.z;
    gemm_mma(g_A0, g_A1, g_A2, g_W0, g_W1, g_W2,
             g_part + (size_t)ks * (B_ * NSEG * H_), H_,
             blockIdx.y * 128, blockIdx.x * 128,
             ks * 256, ks * 256 + 256, sm);
}

// K2b: segproj = tanh(sum of 3 partials + bias) -> bf16x3 splits
__global__ __launch_bounds__(256) void k_proj_fix(const float* __restrict__ bias) {
    const int i = blockIdx.x * 256 + threadIdx.x;      // float4 idx < 196608
    const int c4 = i % (H_ / 4);
    float4 p0 = ((const float4*)g_part)[i];
    float4 p1 = ((const float4*)g_part)[i + 196608];
    float4 p2 = ((const float4*)g_part)[i + 393216];
    float4 bv = ((const float4*)bias)[c4];
    float o[4];
    o[0] = tanhf(p0.x + p1.x + p2.x + bv.x);
    o[1] = tanhf(p0.y + p1.y + p2.y + bv.y);
    o[2] = tanhf(p0.z + p1.z + p2.z + bv.z);
    o[3] = tanhf(p0.w + p1.w + p2.w + bv.w);
    Pack4 e0, e1, e2;
    #pragma unroll
    for (int j = 0; j < 4; j++) split3(o[j], e0.h[j], e1.h[j], e2.h[j]);
    *(unsigned long long*)(g_P0 + (size_t)i * 4) = e0.u;
    *(unsigned long long*)(g_P1 + (size_t)i * 4) = e1.u;
    *(unsigned long long*)(g_P2 + (size_t)i * 4) = e2.u;
}

// K3a: sdot partials, M-tiles pruned by qmax. grid (2, 2, B_*KS_S)
__global__ __launch_bounds__(256) void k_sdot_mma(const int* __restrict__ ind) {
    extern __shared__ __align__(16) __nv_bfloat16 sm[];
    const int b  = blockIdx.z / KS_S;
    const int ks = blockIdx.z % KS_S;
    const int bm = blockIdx.y * 128;
    const int qmax = ind[b * S_ + QPB - 1];
    if (bm > qmax) return;
    const size_t po = (size_t)b * NSEG * H_;
    gemm_mma(g_P0 + po, g_P1 + po, g_P2 + po,
             g_P0 + po, g_P1 + po, g_P2 + po,
             g_spart + (size_t)(b * KS_S + ks) * (NSEG * NSEG), NSEG,
             bm, blockIdx.x * 128,
             ks * 128, ks * 128 + 128, sm);
}

// K3b: g_sdot = sum of KS_S partials (pruned rows). grid (64, B)
__global__ __launch_bounds__(256) void k_sdot_fix(const int* __restrict__ ind) {
    const int b    = blockIdx.y;
    const int qmax = ind[b * S_ + QPB - 1];
    const int row  = blockIdx.x * 4 + (threadIdx.x >> 6);
    if (row > qmax) return;
    const int c4   = threadIdx.x & 63;
    const size_t e = (size_t)row * 64 + c4;
    const size_t base = (size_t)b * KS_S * (NSEG * NSEG / 4);
    float4 s = make_float4(0.f, 0.f, 0.f, 0.f);
    #pragma unroll
    for (int ks = 0; ks < KS_S; ks++) {
        float4 p = ((const float4*)g_spart)[base + (size_t)ks * (NSEG * NSEG / 4) + e];
        s.x += p.x; s.y += p.y; s.z += p.z; s.w += p.w;
    }
    ((float4*)(g_sdot + (size_t)b * NSEG * NSEG))[e] = s;
}

// ---------------------------------------------------------------------------
// K4: per query row: masked logsumexp + argmax over 256 segments
// ---------------------------------------------------------------------------
__global__ __launch_bounds__(256) void k_rows(const int* __restrict__ ind,
                                              const int* __restrict__ clc) {
    __shared__ int s_cnt[NSEG];
    __shared__ int s_fst[NSEG];
    const int lane = threadIdx.x & 31;
    const int gw   = blockIdx.x * 8 + (threadIdx.x >> 5);
    const int b    = gw >> 9;
    const int i    = gw & (QPB - 1);

    if (threadIdx.x < NSEG) {
        s_cnt[threadIdx.x] = g_cnt  [b * NSEG + threadIdx.x];
        s_fst[threadIdx.x] = g_first[b * NSEG + threadIdx.x];
    }
    __syncthreads();

    const int q     = ind[b * S_ + i];
    const int label = clc[b * S_ + i];
    const float* srow = g_sdot + ((size_t)b * NSEG + q) * NSEG;

    float s[8]; int c[8];
    #pragma unroll
    for (int t = 0; t < 8; t++) {
        int v = lane + 32 * t;
        s[t] = __ldg(srow + v);
        c[t] = s_cnt[v];
    }

    float bmax = -INFINITY; int bj = 0x7fffffff;
    #pragma unroll
    for (int t = 0; t < 8; t++) {
        if (c[t] > 0) {
            int j = s_fst[lane + 32 * t];
            if (s[t] > bmax || (s[t] == bmax && j < bj)) { bmax = s[t]; bj = j; }
        }
    }
    #pragma unroll
    for (int off = 16; off; off >>= 1) {
        float os = __shfl_xor_sync(0xffffffffu, bmax, off);
        int   oj = __shfl_xor_sync(0xffffffffu, bj,   off);
        if (os > bmax || (os == bmax && oj < bj)) { bmax = os; bj = oj; }
    }

    float z = 0.0f;
    #pragma unroll
    for (int t = 0; t < 8; t++)
        if (c[t] > 0) z += (float)c[t] * expf(s[t] - bmax);
    #pragma unroll
    for (int off = 16; off; off >>= 1)
        z += __shfl_xor_sync(0xffffffffu, z, off);

    if (lane == 0) {
        int vlab = ind[b * S_ + label];
        float slab = __ldg(srow + vlab);
        float loss = (logf(z) + bmax) - slab;
        if (label < HALF) loss += 1.0e9f;
        g_loss[gw] = loss;
        g_corr[gw] = (bj == label) ? 1 : 0;
    }
}

// ---------------------------------------------------------------------------
// K5: final reduction -> 6 scalars
// ---------------------------------------------------------------------------
__global__ __launch_bounds__(256) void k_final(float* __restrict__ out) {
    __shared__ double sls[256], slt[256];
    __shared__ int    scs[256], sct[256];
    const int t = threadIdx.x;
    double ls = 0.0, lt = 0.0;
    int cs = 0, ct = 0;
    for (int r = t; r < NROWS; r += 256) {
        if (r & 1) { lt += (double)g_loss[r]; ct += g_corr[r]; }
        else       { ls += (double)g_loss[r]; cs += g_corr[r]; }
    }
    sls[t] = ls; slt[t] = lt; scs[t] = cs; sct[t] = ct;
    __syncthreads();
    for (int off = 128; off; off >>= 1) {
        if (t < off) {
            sls[t] += sls[t + off]; slt[t] += slt[t + off];
            scs[t] += scs[t + off]; sct[t] += sct[t + off];
        }
        __syncthreads();
    }
    if (t == 0) {
        const double n = (double)(NROWS / 2);
        out[0] = (float)(sls[0] / n);
        out[1] = (float)scs[0];
        out[2] = (float)(n + 1e-6);
        out[3] = (float)(slt[0] / n);
        out[4] = (float)sct[0];
        out[5] = (float)(n + 1e-6);
    }
}

// ---------------------------------------------------------------------------
extern "C" void kernel_launch(void* const* d_in, const int* in_sizes, int n_in,
                              void* d_out, int out_size) {
    const float* x    = (const float*)d_in[0];
    const float* W    = (const float*)d_in[1];
    const float* bias = (const float*)d_in[2];
    const int*   ind  = (const int*)  d_in[3];
    const int*   clc  = (const int*)  d_in[4];
    float* out = (float*)d_out;
    (void)in_sizes; (void)n_in; (void)out_size;

    static bool attr_set = false;
    if (!attr_set) {
        cudaFuncSetAttribute(k_proj_mma, cudaFuncAttributeMaxDynamicSharedMemorySize, SMEM_MMA);
        cudaFuncSetAttribute(k_sdot_mma, cudaFuncAttributeMaxDynamicSharedMemorySize, SMEM_MMA);
        attr_set = true;
    }

    dim3 g1(NSEG, B_);
    k_segsum<<<g1, 192>>>(x, ind);

    k_convW<<<(H_ * H_ / 4) / 256, 256>>>(W);

    dim3 g2(H_ / 128, (B_ * NSEG) / 128, KS_P);      // (6, 8, 3) = 144 blocks
    k_proj_mma<<<g2, 256, SMEM_MMA>>>();
    k_proj_fix<<<(B_ * NSEG * H_ / 4) / 256, 256>>>(bias);

    dim3 g3(NSEG / 128, NSEG / 128, B_ * KS_S);      // (2, 2, 24)
    k_sdot_mma<<<g3, 256, SMEM_MMA>>>(ind);
    dim3 g3f(64, B_);
    k_sdot_fix<<<g3f, 256>>>(ind);

    k_rows<<<NROWS / 8, 256>>>(ind, clc);

    k_final<<<1, 256>>>(out);
}

// round 8
// speedup vs baseline: 2.8360x; 1.3095x over previous
#include <cuda_runtime.h>
#include <cuda_bf16.h>
#include <math.h>
#include <stdint.h>

#define B_    4
#define S_    2048
#define H_    768
#define NSEG  256
#define NROWS 2048
#define QPB   512
#define HALF  1024
#define KS_P  3
#define KS_S  6

#define SROW  24               // smem row stride in bf16 (16 data + 8 pad = 48B)
#define SLABE (128 * SROW)
#define SMEM_MMA (2 * 4 * SLABE * 2)   // 2 stages x (2A + 2B) slabs = 49152 B
#define NCONVW 576             // convW blocks in fused prep kernel

// -------- scratch --------
__device__ __nv_bfloat16 g_A0[B_ * NSEG * H_];
__device__ __nv_bfloat16 g_A1[B_ * NSEG * H_];
__device__ __nv_bfloat16 g_W0[H_ * H_];
__device__ __nv_bfloat16 g_W1[H_ * H_];
__device__ __nv_bfloat16 g_P0[B_ * NSEG * H_];
__device__ __nv_bfloat16 g_P1[B_ * NSEG * H_];
__device__ float g_part [KS_P * B_ * NSEG * H_];
__device__ float g_spart[KS_S * B_ * NSEG * NSEG];
__device__ float g_sdot [B_ * NSEG * NSEG];
__device__ int   g_cnt  [B_ * NSEG];
__device__ int   g_first[B_ * NSEG];
__device__ float g_loss [NROWS];
__device__ int   g_corr [NROWS];

__device__ __forceinline__ void split2(float x, __nv_bfloat16& b0, __nv_bfloat16& b1) {
    b0 = __float2bfloat16(x);
    b1 = __float2bfloat16(x - __bfloat162float(b0));
}
union Pack4 { __nv_bfloat16 h[4]; unsigned long long u; };

__device__ __forceinline__ void mma16816(float* c,
                                         uint32_t a0, uint32_t a1, uint32_t a2, uint32_t a3,
                                         uint32_t b0, uint32_t b1) {
    asm volatile(
        "mma.sync.aligned.m16n8k16.row.col.f32.bf16.bf16.f32 "
        "{%0,%1,%2,%3}, {%4,%5,%6,%7}, {%8,%9}, {%0,%1,%2,%3};"
        : "+f"(c[0]), "+f"(c[1]), "+f"(c[2]), "+f"(c[3])
        : "r"(a0), "r"(a1), "r"(a2), "r"(a3), "r"(b0), "r"(b1));
}
__device__ __forceinline__ void ldsm4(uint32_t& d0, uint32_t& d1, uint32_t& d2,
                                      uint32_t& d3, const void* p) {
    uint32_t addr = (uint32_t)__cvta_generic_to_shared(p);
    asm volatile("ldmatrix.sync.aligned.m8n8.x4.shared.b16 {%0,%1,%2,%3}, [%4];"
                 : "=r"(d0), "=r"(d1), "=r"(d2), "=r"(d3) : "r"(addr));
}

// ---------------------------------------------------------------------------
// K1: fused prep — blocks [0,NCONVW): W->bf16x2; blocks >= NCONVW: segsum
// ---------------------------------------------------------------------------
__global__ __launch_bounds__(256) void k_prep(const float* __restrict__ x,
                                              const float* __restrict__ W,
                                              const int* __restrict__ ind) {
    if (blockIdx.x < NCONVW) {
        const int i = blockIdx.x * 256 + threadIdx.x;    // float4 idx < 147456
        float4 w = ((const float4*)W)[i];
        Pack4 p0, p1;
        float a[4] = {w.x, w.y, w.z, w.w};
        #pragma unroll
        for (int j = 0; j < 4; j++) split2(a[j], p0.h[j], p1.h[j]);
        *(unsigned long long*)(g_W0 + (size_t)i * 4) = p0.u;
        *(unsigned long long*)(g_W1 + (size_t)i * 4) = p1.u;
        return;
    }
    const int sb = blockIdx.x - NCONVW;                  // 0..1023
    const int v = sb & (NSEG - 1);
    const int b = sb >> 8;
    const int t = threadIdx.x;
    if (t >= 192) return;
    const int* row = ind + b * S_;

    int lo, hi;
    { int l = 0, r = S_;
      while (l < r) { int m = (l + r) >> 1; if (row[m] < v) l = m + 1; else r = m; }
      lo = l; }
    { int l = lo, r = S_;
      while (l < r) { int m = (l + r) >> 1; if (row[m] <= v) l = m + 1; else r = m; }
      hi = l; }

    const int H4 = H_ / 4;
    float4 acc = make_float4(0.f, 0.f, 0.f, 0.f);
    const float4* xp = (const float4*)(x + ((size_t)b * S_ + lo) * H_) + t;

    int i = lo;
    for (; i + 8 <= hi; i += 8) {
        float4 u0 = xp[0];      float4 u1 = xp[H4];
        float4 u2 = xp[2 * H4]; float4 u3 = xp[3 * H4];
        float4 u4 = xp[4 * H4]; float4 u5 = xp[5 * H4];
        float4 u6 = xp[6 * H4]; float4 u7 = xp[7 * H4];
        xp += 8 * H4;
        acc.x += u0.x; acc.y += u0.y; acc.z += u0.z; acc.w += u0.w;
        acc.x += u1.x; acc.y += u1.y; acc.z += u1.z; acc.w += u1.w;
        acc.x += u2.x; acc.y += u2.y; acc.z += u2.z; acc.w += u2.w;
        acc.x += u3.x; acc.y += u3.y; acc.z += u3.z; acc.w += u3.w;
        acc.x += u4.x; acc.y += u4.y; acc.z += u4.z; acc.w += u4.w;
        acc.x += u5.x; acc.y += u5.y; acc.z += u5.z; acc.w += u5.w;
        acc.x += u6.x; acc.y += u6.y; acc.z += u6.z; acc.w += u6.w;
        acc.x += u7.x; acc.y += u7.y; acc.z += u7.z; acc.w += u7.w;
    }
    for (; i < hi; i++) {
        float4 u = *xp; xp += H4;
        acc.x += u.x; acc.y += u.y; acc.z += u.z; acc.w += u.w;
    }

    Pack4 p0, p1;
    float a[4] = {acc.x, acc.y, acc.z, acc.w};
    #pragma unroll
    for (int j = 0; j < 4; j++) split2(a[j], p0.h[j], p1.h[j]);
    const size_t e = ((size_t)b * NSEG + v) * H_ + t * 4;
    *(unsigned long long*)(g_A0 + e) = p0.u;
    *(unsigned long long*)(g_A1 + e) = p1.u;

    if (t == 0) {
        int lo2 = lo > HALF ? lo : HALF;
        int c   = hi - lo2; if (c < 0) c = 0;
        g_cnt  [b * NSEG + v] = c;
        g_first[b * NSEG + v] = lo2;
    }
}

// ---------------------------------------------------------------------------
// mma GEMM: Cpart[128x128] = A0B0 + A0B1 + A1B0 (bf16x2, 3 cross terms)
// 8 warps (2x4), warp tile 64x32, ldmatrix.x4 fragment loads, dbl-buffered.
// ---------------------------------------------------------------------------
__device__ __forceinline__ void gemm_mma(
    const __nv_bfloat16* A0g, const __nv_bfloat16* A1g,
    const __nv_bfloat16* B0g, const __nv_bfloat16* B1g,
    float* Cout, int ldc, int bm, int bn, int kb, int ke, __nv_bfloat16* sm)
{
    const int tid  = threadIdx.x;
    const int wid  = tid >> 5, lane = tid & 31;
    const int wm   = wid & 1, wn = wid >> 1;
    const int gid  = lane >> 2, tid4 = lane & 3;
    const int lrow = tid >> 1;
    const int lhalf = (tid & 1) * 8;
    const int lml  = lane & 15;           // ldmatrix row within 16
    const int lmk  = (lane >> 4) * 8;     // ldmatrix k offset

    const __nv_bfloat16* Ag[2] = {A0g, A1g};
    const __nv_bfloat16* Bg[2] = {B0g, B1g};

    float acc[4][4][4];
    #pragma unroll
    for (int i = 0; i < 4; i++)
        #pragma unroll
        for (int j = 0; j < 4; j++)
            #pragma unroll
            for (int k = 0; k < 4; k++) acc[i][j][k] = 0.f;

    uint4 ra[2], rb[2];
    #pragma unroll
    for (int s = 0; s < 2; s++) {
        ra[s] = *(const uint4*)(Ag[s] + (size_t)(bm + lrow) * H_ + kb + lhalf);
        rb[s] = *(const uint4*)(Bg[s] + (size_t)(bn + lrow) * H_ + kb + lhalf);
    }

    int stage = 0;
    for (int k0 = kb; k0 < ke; k0 += 16) {
        __nv_bfloat16* base = sm + stage * 4 * SLABE;
        #pragma unroll
        for (int s = 0; s < 2; s++) {
            *(uint4*)(base + s * SLABE + lrow * SROW + lhalf)       = ra[s];
            *(uint4*)(base + (2 + s) * SLABE + lrow * SROW + lhalf) = rb[s];
        }
        __syncthreads();

        if (k0 + 16 < ke) {
            #pragma unroll
            for (int s = 0; s < 2; s++) {
                ra[s] = *(const uint4*)(Ag[s] + (size_t)(bm + lrow) * H_ + k0 + 16 + lhalf);
                rb[s] = *(const uint4*)(Bg[s] + (size_t)(bn + lrow) * H_ + k0 + 16 + lhalf);
            }
        }

        // ldmatrix: A fragments for both splits, all 4 m-subtiles
        uint32_t af[2][4][4];
        #pragma unroll
        for (int s = 0; s < 2; s++) {
            const __nv_bfloat16* As_ = base + s * SLABE;
            #pragma unroll
            for (int mi = 0; mi < 4; mi++) {
                const __nv_bfloat16* p = As_ + (wm * 64 + mi * 16 + lml) * SROW + lmk;
                ldsm4(af[s][mi][0], af[s][mi][1], af[s][mi][2], af[s][mi][3], p);
            }
        }
        // B fragments for both splits: one x4 covers 16 n (= 2 ni) x 16 k
        uint32_t bfr[2][4][2];
        #pragma unroll
        for (int s = 0; s < 2; s++) {
            const __nv_bfloat16* Bs_ = base + (2 + s) * SLABE;
            #pragma unroll
            for (int h = 0; h < 2; h++) {
                const __nv_bfloat16* p = Bs_ + (wn * 32 + h * 16 + lml) * SROW + lmk;
                ldsm4(bfr[s][h * 2 + 0][0], bfr[s][h * 2 + 1][0],
                      bfr[s][h * 2 + 0][1], bfr[s][h * 2 + 1][1], p);
            }
        }

        // 3 cross terms: (0,0), (0,1), (1,0)
        #pragma unroll
        for (int mi = 0; mi < 4; mi++)
            #pragma unroll
            for (int ni = 0; ni < 4; ni++) {
                mma16816(acc[mi][ni], af[0][mi][0], af[0][mi][1], af[0][mi][2], af[0][mi][3],
                         bfr[0][ni][0], bfr[0][ni][1]);
                mma16816(acc[mi][ni], af[0][mi][0], af[0][mi][1], af[0][mi][2], af[0][mi][3],
                         bfr[1][ni][0], bfr[1][ni][1]);
                mma16816(acc[mi][ni], af[1][mi][0], af[1][mi][1], af[1][mi][2], af[1][mi][3],
                         bfr[0][ni][0], bfr[0][ni][1]);
            }
        __syncthreads();
        stage ^= 1;
    }

    #pragma unroll
    for (int mi = 0; mi < 4; mi++) {
        int r0 = bm + wm * 64 + mi * 16 + gid;
        #pragma unroll
        for (int ni = 0; ni < 4; ni++) {
            int c = bn + wn * 32 + ni * 8 + tid4 * 2;
            *(float2*)(Cout + (size_t)r0 * ldc + c)       = make_float2(acc[mi][ni][0], acc[mi][ni][1]);
            *(float2*)(Cout + (size_t)(r0 + 8) * ldc + c) = make_float2(acc[mi][ni][2], acc[mi][ni][3]);
        }
    }
}

// K2a: proj partials. grid (6, 8, KS_P) = 144 blocks
__global__ __launch_bounds__(256) void k_proj_mma() {
    extern __shared__ __align__(16) __nv_bfloat16 sm[];
    const int ks = blockIdx.z;
    gemm_mma(g_A0, g_A1, g_W0, g_W1,
             g_part + (size_t)ks * (B_ * NSEG * H_), H_,
             blockIdx.y * 128, blockIdx.x * 128,
             ks * 256, ks * 256 + 256, sm);
}

// K2b: segproj = tanh(sum of 3 partials + bias) -> bf16x2 splits
__global__ __launch_bounds__(256) void k_proj_fix(const float* __restrict__ bias) {
    const int i = blockIdx.x * 256 + threadIdx.x;
    const int c4 = i % (H_ / 4);
    float4 p0 = ((const float4*)g_part)[i];
    float4 p1 = ((const float4*)g_part)[i + 196608];
    float4 p2 = ((const float4*)g_part)[i + 393216];
    float4 bv = ((const float4*)bias)[c4];
    float o[4];
    o[0] = tanhf(p0.x + p1.x + p2.x + bv.x);
    o[1] = tanhf(p0.y + p1.y + p2.y + bv.y);
    o[2] = tanhf(p0.z + p1.z + p2.z + bv.z);
    o[3] = tanhf(p0.w + p1.w + p2.w + bv.w);
    Pack4 e0, e1;
    #pragma unroll
    for (int j = 0; j < 4; j++) split2(o[j], e0.h[j], e1.h[j]);
    *(unsigned long long*)(g_P0 + (size_t)i * 4) = e0.u;
    *(unsigned long long*)(g_P1 + (size_t)i * 4) = e1.u;
}

// K3a: sdot partials, M-tiles pruned by qmax. grid (2, 2, B_*KS_S)
__global__ __launch_bounds__(256) void k_sdot_mma(const int* __restrict__ ind) {
    extern __shared__ __align__(16) __nv_bfloat16 sm[];
    const int b  = blockIdx.z / KS_S;
    const int ks = blockIdx.z % KS_S;
    const int bm = blockIdx.y * 128;
    const int qmax = ind[b * S_ + QPB - 1];
    if (bm > qmax) return;
    const size_t po = (size_t)b * NSEG * H_;
    gemm_mma(g_P0 + po, g_P1 + po, g_P0 + po, g_P1 + po,
             g_spart + (size_t)(b * KS_S + ks) * (NSEG * NSEG), NSEG,
             bm, blockIdx.x * 128,
             ks * 128, ks * 128 + 128, sm);
}

// K3b: g_sdot = sum of KS_S partials (pruned rows). grid (64, B)
__global__ __launch_bounds__(256) void k_sdot_fix(const int* __restrict__ ind) {
    const int b    = blockIdx.y;
    const int qmax = ind[b * S_ + QPB - 1];
    const int row  = blockIdx.x * 4 + (threadIdx.x >> 6);
    if (row > qmax) return;
    const int c4   = threadIdx.x & 63;
    const size_t e = (size_t)row * 64 + c4;
    const size_t base = (size_t)b * KS_S * (NSEG * NSEG / 4);
    float4 s = make_float4(0.f, 0.f, 0.f, 0.f);
    #pragma unroll
    for (int ks = 0; ks < KS_S; ks++) {
        float4 p = ((const float4*)g_spart)[base + (size_t)ks * (NSEG * NSEG / 4) + e];
        s.x += p.x; s.y += p.y; s.z += p.z; s.w += p.w;
    }
    ((float4*)(g_sdot + (size_t)b * NSEG * NSEG))[e] = s;
}

// ---------------------------------------------------------------------------
// K4: per query row: masked logsumexp + argmax over 256 segments
// ---------------------------------------------------------------------------
__global__ __launch_bounds__(256) void k_rows(const int* __restrict__ ind,
                                              const int* __restrict__ clc) {
    __shared__ int s_cnt[NSEG];
    __shared__ int s_fst[NSEG];
    const int lane = threadIdx.x & 31;
    const int gw   = blockIdx.x * 8 + (threadIdx.x >> 5);
    const int b    = gw >> 9;
    const int i    = gw & (QPB - 1);

    if (threadIdx.x < NSEG) {
        s_cnt[threadIdx.x] = g_cnt  [b * NSEG + threadIdx.x];
        s_fst[threadIdx.x] = g_first[b * NSEG + threadIdx.x];
    }
    __syncthreads();

    const int q     = ind[b * S_ + i];
    const int label = clc[b * S_ + i];
    const float* srow = g_sdot + ((size_t)b * NSEG + q) * NSEG;

    float s[8]; int c[8];
    #pragma unroll
    for (int t = 0; t < 8; t++) {
        int v = lane + 32 * t;
        s[t] = __ldg(srow + v);
        c[t] = s_cnt[v];
    }

    float bmax = -INFINITY; int bj = 0x7fffffff;
    #pragma unroll
    for (int t = 0; t < 8; t++) {
        if (c[t] > 0) {
            int j = s_fst[lane + 32 * t];
            if (s[t] > bmax || (s[t] == bmax && j < bj)) { bmax = s[t]; bj = j; }
        }
    }
    #pragma unroll
    for (int off = 16; off; off >>= 1) {
        float os = __shfl_xor_sync(0xffffffffu, bmax, off);
        int   oj = __shfl_xor_sync(0xffffffffu, bj,   off);
        if (os > bmax || (os == bmax && oj < bj)) { bmax = os; bj = oj; }
    }

    float z = 0.0f;
    #pragma unroll
    for (int t = 0; t < 8; t++)
        if (c[t] > 0) z += (float)c[t] * expf(s[t] - bmax);
    #pragma unroll
    for (int off = 16; off; off >>= 1)
        z += __shfl_xor_sync(0xffffffffu, z, off);

    if (lane == 0) {
        int vlab = ind[b * S_ + label];
        float slab = __ldg(srow + vlab);
        float loss = (logf(z) + bmax) - slab;
        if (label < HALF) loss += 1.0e9f;
        g_loss[gw] = loss;
        g_corr[gw] = (bj == label) ? 1 : 0;
    }
}

// ---------------------------------------------------------------------------
// K5: final reduction -> 6 scalars
// ---------------------------------------------------------------------------
__global__ __launch_bounds__(256) void k_final(float* __restrict__ out) {
    __shared__ double sls[256], slt[256];
    __shared__ int    scs[256], sct[256];
    const int t = threadIdx.x;
    double ls = 0.0, lt = 0.0;
    int cs = 0, ct = 0;
    for (int r = t; r < NROWS; r += 256) {
        if (r & 1) { lt += (double)g_loss[r]; ct += g_corr[r]; }
        else       { ls += (double)g_loss[r]; cs += g_corr[r]; }
    }
    sls[t] = ls; slt[t] = lt; scs[t] = cs; sct[t] = ct;
    __syncthreads();
    for (int off = 128; off; off >>= 1) {
        if (t < off) {
            sls[t] += sls[t + off]; slt[t] += slt[t + off];
            scs[t] += scs[t + off]; sct[t] += sct[t + off];
        }
        __syncthreads();
    }
    if (t == 0) {
        const double n = (double)(NROWS / 2);
        out[0] = (float)(sls[0] / n);
        out[1] = (float)scs[0];
        out[2] = (float)(n + 1e-6);
        out[3] = (float)(slt[0] / n);
        out[4] = (float)sct[0];
        out[5] = (float)(n + 1e-6);
    }
}

// ---------------------------------------------------------------------------
extern "C" void kernel_launch(void* const* d_in, const int* in_sizes, int n_in,
                              void* d_out, int out_size) {
    const float* x    = (const float*)d_in[0];
    const float* W    = (const float*)d_in[1];
    const float* bias = (const float*)d_in[2];
    const int*   ind  = (const int*)  d_in[3];
    const int*   clc  = (const int*)  d_in[4];
    float* out = (float*)d_out;
    (void)in_sizes; (void)n_in; (void)out_size;

    static bool attr_set = false;
    if (!attr_set) {
        cudaFuncSetAttribute(k_proj_mma, cudaFuncAttributeMaxDynamicSharedMemorySize, SMEM_MMA);
        cudaFuncSetAttribute(k_sdot_mma, cudaFuncAttributeMaxDynamicSharedMemorySize, SMEM_MMA);
        attr_set = true;
    }

    k_prep<<<NCONVW + NSEG * B_, 256>>>(x, W, ind);

    dim3 g2(H_ / 128, (B_ * NSEG) / 128, KS_P);      // (6, 8, 3) = 144 blocks
    k_proj_mma<<<g2, 256, SMEM_MMA>>>();
    k_proj_fix<<<(B_ * NSEG * H_ / 4) / 256, 256>>>(bias);

    dim3 g3(NSEG / 128, NSEG / 128, B_ * KS_S);      // (2, 2, 24)
    k_sdot_mma<<<g3, 256, SMEM_MMA>>>(ind);
    dim3 g3f(64, B_);
    k_sdot_fix<<<g3f, 256>>>(ind);

    k_rows<<<NROWS / 8, 256>>>(ind, clc);

    k_final<<<1, 256>>>(out);
}

// round 9
// speedup vs baseline: 3.0769x; 1.0849x over previous
#include <cuda_runtime.h>
#include <cuda_bf16.h>
#include <math.h>
#include <stdint.h>

#define B_    4
#define S_    2048
#define H_    768
#define NSEG  256
#define NROWS 2048
#define QPB   512
#define HALF  1024
#define KS_P  3
#define KS_S  12

#define SROW  24               // smem row stride in bf16 (16 data + 8 pad = 48B)
#define SLABE (128 * SROW)
#define SLAB64 (64 * SROW)
#define SMEM_MMA (2 * 4 * SLABE * 2)            // proj: 49152 B
#define SMEM_M64 (2 * 2 * (SLAB64 + SLABE) * 2) // sdot: 36864 B
#define NCONVW 576

// -------- scratch --------
__device__ __nv_bfloat16 g_A0[B_ * NSEG * H_];
__device__ __nv_bfloat16 g_A1[B_ * NSEG * H_];
__device__ __nv_bfloat16 g_W0[H_ * H_];
__device__ __nv_bfloat16 g_W1[H_ * H_];
__device__ __nv_bfloat16 g_P0[B_ * NSEG * H_];
__device__ __nv_bfloat16 g_P1[B_ * NSEG * H_];
__device__ float g_part [KS_P * B_ * NSEG * H_];
__device__ float g_spart[KS_S * B_ * NSEG * NSEG];
__device__ float g_sdot [B_ * NSEG * NSEG];
__device__ int   g_cnt  [B_ * NSEG];
__device__ int   g_first[B_ * NSEG];
__device__ float g_loss [NROWS];
__device__ int   g_corr [NROWS];

__device__ __forceinline__ void split2(float x, __nv_bfloat16& b0, __nv_bfloat16& b1) {
    b0 = __float2bfloat16(x);
    b1 = __float2bfloat16(x - __bfloat162float(b0));
}
union Pack4 { __nv_bfloat16 h[4]; unsigned long long u; };

__device__ __forceinline__ void mma16816(float* c,
                                         uint32_t a0, uint32_t a1, uint32_t a2, uint32_t a3,
                                         uint32_t b0, uint32_t b1) {
    asm volatile(
        "mma.sync.aligned.m16n8k16.row.col.f32.bf16.bf16.f32 "
        "{%0,%1,%2,%3}, {%4,%5,%6,%7}, {%8,%9}, {%0,%1,%2,%3};"
        : "+f"(c[0]), "+f"(c[1]), "+f"(c[2]), "+f"(c[3])
        : "r"(a0), "r"(a1), "r"(a2), "r"(a3), "r"(b0), "r"(b1));
}
__device__ __forceinline__ void ldsm4(uint32_t& d0, uint32_t& d1, uint32_t& d2,
                                      uint32_t& d3, const void* p) {
    uint32_t addr = (uint32_t)__cvta_generic_to_shared(p);
    asm volatile("ldmatrix.sync.aligned.m8n8.x4.shared.b16 {%0,%1,%2,%3}, [%4];"
                 : "=r"(d0), "=r"(d1), "=r"(d2), "=r"(d3) : "r"(addr));
}

// ---------------------------------------------------------------------------
// K1: fused prep — blocks [0,NCONVW): W->bf16x2; blocks >= NCONVW: segsum
// ---------------------------------------------------------------------------
__global__ __launch_bounds__(256) void k_prep(const float* __restrict__ x,
                                              const float* __restrict__ W,
                                              const int* __restrict__ ind) {
    if (blockIdx.x < NCONVW) {
        const int i = blockIdx.x * 256 + threadIdx.x;
        float4 w = ((const float4*)W)[i];
        Pack4 p0, p1;
        float a[4] = {w.x, w.y, w.z, w.w};
        #pragma unroll
        for (int j = 0; j < 4; j++) split2(a[j], p0.h[j], p1.h[j]);
        *(unsigned long long*)(g_W0 + (size_t)i * 4) = p0.u;
        *(unsigned long long*)(g_W1 + (size_t)i * 4) = p1.u;
        return;
    }
    const int sb = blockIdx.x - NCONVW;
    const int v = sb & (NSEG - 1);
    const int b = sb >> 8;
    const int t = threadIdx.x;
    if (t >= 192) return;
    const int* row = ind + b * S_;

    int lo, hi;
    { int l = 0, r = S_;
      while (l < r) { int m = (l + r) >> 1; if (row[m] < v) l = m + 1; else r = m; }
      lo = l; }
    { int l = lo, r = S_;
      while (l < r) { int m = (l + r) >> 1; if (row[m] <= v) l = m + 1; else r = m; }
      hi = l; }

    const int H4 = H_ / 4;
    float4 acc = make_float4(0.f, 0.f, 0.f, 0.f);
    const float4* xp = (const float4*)(x + ((size_t)b * S_ + lo) * H_) + t;

    int i = lo;
    for (; i + 8 <= hi; i += 8) {
        float4 u0 = xp[0];      float4 u1 = xp[H4];
        float4 u2 = xp[2 * H4]; float4 u3 = xp[3 * H4];
        float4 u4 = xp[4 * H4]; float4 u5 = xp[5 * H4];
        float4 u6 = xp[6 * H4]; float4 u7 = xp[7 * H4];
        xp += 8 * H4;
        acc.x += u0.x; acc.y += u0.y; acc.z += u0.z; acc.w += u0.w;
        acc.x += u1.x; acc.y += u1.y; acc.z += u1.z; acc.w += u1.w;
        acc.x += u2.x; acc.y += u2.y; acc.z += u2.z; acc.w += u2.w;
        acc.x += u3.x; acc.y += u3.y; acc.z += u3.z; acc.w += u3.w;
        acc.x += u4.x; acc.y += u4.y; acc.z += u4.z; acc.w += u4.w;
        acc.x += u5.x; acc.y += u5.y; acc.z += u5.z; acc.w += u5.w;
        acc.x += u6.x; acc.y += u6.y; acc.z += u6.z; acc.w += u6.w;
        acc.x += u7.x; acc.y += u7.y; acc.z += u7.z; acc.w += u7.w;
    }
    for (; i < hi; i++) {
        float4 u = *xp; xp += H4;
        acc.x += u.x; acc.y += u.y; acc.z += u.z; acc.w += u.w;
    }

    Pack4 p0, p1;
    float a[4] = {acc.x, acc.y, acc.z, acc.w};
    #pragma unroll
    for (int j = 0; j < 4; j++) split2(a[j], p0.h[j], p1.h[j]);
    const size_t e = ((size_t)b * NSEG + v) * H_ + t * 4;
    *(unsigned long long*)(g_A0 + e) = p0.u;
    *(unsigned long long*)(g_A1 + e) = p1.u;

    if (t == 0) {
        int lo2 = lo > HALF ? lo : HALF;
        int c   = hi - lo2; if (c < 0) c = 0;
        g_cnt  [b * NSEG + v] = c;
        g_first[b * NSEG + v] = lo2;
    }
}

// ---------------------------------------------------------------------------
// proj GEMM (M128 x N128): 3 cross terms, ldmatrix, double-buffered
// ---------------------------------------------------------------------------
__device__ __forceinline__ void gemm_mma(
    const __nv_bfloat16* A0g, const __nv_bfloat16* A1g,
    const __nv_bfloat16* B0g, const __nv_bfloat16* B1g,
    float* Cout, int ldc, int bm, int bn, int kb, int ke, __nv_bfloat16* sm)
{
    const int tid  = threadIdx.x;
    const int wid  = tid >> 5, lane = tid & 31;
    const int wm   = wid & 1, wn = wid >> 1;
    const int gid  = lane >> 2, tid4 = lane & 3;
    const int lrow = tid >> 1;
    const int lhalf = (tid & 1) * 8;
    const int lml  = lane & 15;
    const int lmk  = (lane >> 4) * 8;

    const __nv_bfloat16* Ag[2] = {A0g, A1g};
    const __nv_bfloat16* Bg[2] = {B0g, B1g};

    float acc[4][4][4];
    #pragma unroll
    for (int i = 0; i < 4; i++)
        #pragma unroll
        for (int j = 0; j < 4; j++)
            #pragma unroll
            for (int k = 0; k < 4; k++) acc[i][j][k] = 0.f;

    uint4 ra[2], rb[2];
    #pragma unroll
    for (int s = 0; s < 2; s++) {
        ra[s] = *(const uint4*)(Ag[s] + (size_t)(bm + lrow) * H_ + kb + lhalf);
        rb[s] = *(const uint4*)(Bg[s] + (size_t)(bn + lrow) * H_ + kb + lhalf);
    }

    int stage = 0;
    for (int k0 = kb; k0 < ke; k0 += 16) {
        __nv_bfloat16* base = sm + stage * 4 * SLABE;
        #pragma unroll
        for (int s = 0; s < 2; s++) {
            *(uint4*)(base + s * SLABE + lrow * SROW + lhalf)       = ra[s];
            *(uint4*)(base + (2 + s) * SLABE + lrow * SROW + lhalf) = rb[s];
        }
        __syncthreads();

        if (k0 + 16 < ke) {
            #pragma unroll
            for (int s = 0; s < 2; s++) {
                ra[s] = *(const uint4*)(Ag[s] + (size_t)(bm + lrow) * H_ + k0 + 16 + lhalf);
                rb[s] = *(const uint4*)(Bg[s] + (size_t)(bn + lrow) * H_ + k0 + 16 + lhalf);
            }
        }

        uint32_t af[2][4][4];
        #pragma unroll
        for (int s = 0; s < 2; s++) {
            const __nv_bfloat16* As_ = base + s * SLABE;
            #pragma unroll
            for (int mi = 0; mi < 4; mi++) {
                const __nv_bfloat16* p = As_ + (wm * 64 + mi * 16 + lml) * SROW + lmk;
                ldsm4(af[s][mi][0], af[s][mi][1], af[s][mi][2], af[s][mi][3], p);
            }
        }
        uint32_t bfr[2][4][2];
        #pragma unroll
        for (int s = 0; s < 2; s++) {
            const __nv_bfloat16* Bs_ = base + (2 + s) * SLABE;
            #pragma unroll
            for (int h = 0; h < 2; h++) {
                const __nv_bfloat16* p = Bs_ + (wn * 32 + h * 16 + lml) * SROW + lmk;
                ldsm4(bfr[s][h * 2 + 0][0], bfr[s][h * 2 + 1][0],
                      bfr[s][h * 2 + 0][1], bfr[s][h * 2 + 1][1], p);
            }
        }

        #pragma unroll
        for (int mi = 0; mi < 4; mi++)
            #pragma unroll
            for (int ni = 0; ni < 4; ni++) {
                mma16816(acc[mi][ni], af[0][mi][0], af[0][mi][1], af[0][mi][2], af[0][mi][3],
                         bfr[0][ni][0], bfr[0][ni][1]);
                mma16816(acc[mi][ni], af[0][mi][0], af[0][mi][1], af[0][mi][2], af[0][mi][3],
                         bfr[1][ni][0], bfr[1][ni][1]);
                mma16816(acc[mi][ni], af[1][mi][0], af[1][mi][1], af[1][mi][2], af[1][mi][3],
                         bfr[0][ni][0], bfr[0][ni][1]);
            }
        __syncthreads();
        stage ^= 1;
    }

    #pragma unroll
    for (int mi = 0; mi < 4; mi++) {
        int r0 = bm + wm * 64 + mi * 16 + gid;
        #pragma unroll
        for (int ni = 0; ni < 4; ni++) {
            int c = bn + wn * 32 + ni * 8 + tid4 * 2;
            *(float2*)(Cout + (size_t)r0 * ldc + c)       = make_float2(acc[mi][ni][0], acc[mi][ni][1]);
            *(float2*)(Cout + (size_t)(r0 + 8) * ldc + c) = make_float2(acc[mi][ni][2], acc[mi][ni][3]);
        }
    }
}

// K2a: proj partials. grid (6, 8, KS_P) = 144 blocks
__global__ __launch_bounds__(256) void k_proj_mma() {
    extern __shared__ __align__(16) __nv_bfloat16 sm[];
    const int ks = blockIdx.z;
    gemm_mma(g_A0, g_A1, g_W0, g_W1,
             g_part + (size_t)ks * (B_ * NSEG * H_), H_,
             blockIdx.y * 128, blockIdx.x * 128,
             ks * 256, ks * 256 + 256, sm);
}

// K2b: segproj = tanh(sum of 3 partials + bias) -> bf16x2 (2 float4/thread)
__global__ __launch_bounds__(256) void k_proj_fix(const float* __restrict__ bias) {
    #pragma unroll
    for (int u = 0; u < 2; u++) {
        const int i = blockIdx.x * 512 + u * 256 + threadIdx.x;
        const int c4 = i % (H_ / 4);
        float4 p0 = ((const float4*)g_part)[i];
        float4 p1 = ((const float4*)g_part)[i + 196608];
        float4 p2 = ((const float4*)g_part)[i + 393216];
        float4 bv = ((const float4*)bias)[c4];
        float o[4];
        o[0] = tanhf(p0.x + p1.x + p2.x + bv.x);
        o[1] = tanhf(p0.y + p1.y + p2.y + bv.y);
        o[2] = tanhf(p0.z + p1.z + p2.z + bv.z);
        o[3] = tanhf(p0.w + p1.w + p2.w + bv.w);
        Pack4 e0, e1;
        #pragma unroll
        for (int j = 0; j < 4; j++) split2(o[j], e0.h[j], e1.h[j]);
        *(unsigned long long*)(g_P0 + (size_t)i * 4) = e0.u;
        *(unsigned long long*)(g_P1 + (size_t)i * 4) = e1.u;
    }
}

// ---------------------------------------------------------------------------
// sdot GEMM (M64 x N128): 8 warps 2x4, warp tile 32x32
// ---------------------------------------------------------------------------
__global__ __launch_bounds__(256) void k_sdot_mma(const int* __restrict__ ind) {
    extern __shared__ __align__(16) __nv_bfloat16 sm[];
    const int b  = blockIdx.z / KS_S;
    const int ks = blockIdx.z % KS_S;
    const int bm = blockIdx.y * 64;
    const int bn = blockIdx.x * 128;
    const int qmax = ind[b * S_ + QPB - 1];
    if (bm > qmax) return;

    const size_t po = (size_t)b * NSEG * H_;
    const __nv_bfloat16* Ag[2] = {g_P0 + po, g_P1 + po};
    float* Cout = g_spart + (size_t)(b * KS_S + ks) * (NSEG * NSEG);
    const int kb = ks * 64, ke = kb + 64;

    const int tid  = threadIdx.x;
    const int wid  = tid >> 5, lane = tid & 31;
    const int wm   = wid & 1, wn = wid >> 1;
    const int gid  = lane >> 2, tid4 = lane & 3;
    const int lml  = lane & 15;
    const int lmk  = (lane >> 4) * 8;
    // A loader: 256 uint4 total (2 splits x 64 rows x 2 halves)
    const int a_s = tid >> 7, a_r = (tid >> 1) & 63, a_h = (tid & 1) * 8;
    // B loader: 512 uint4 -> 2 per thread
    const int stagesz = 2 * SLAB64 + 2 * SLABE;

    float acc[2][4][4];
    #pragma unroll
    for (int i = 0; i < 2; i++)
        #pragma unroll
        for (int j = 0; j < 4; j++)
            #pragma unroll
            for (int k = 0; k < 4; k++) acc[i][j][k] = 0.f;

    uint4 ra, rb[2];
    ra = *(const uint4*)(Ag[a_s] + (size_t)(bm + a_r) * H_ + kb + a_h);
    #pragma unroll
    for (int it = 0; it < 2; it++) {
        int i = tid + it * 256;
        int s = i >> 8, rem = i & 255, r = rem >> 1, h = (rem & 1) * 8;
        rb[it] = *(const uint4*)(Ag[s] + (size_t)(bn + r) * H_ + kb + h);
    }

    int stage = 0;
    for (int k0 = kb; k0 < ke; k0 += 16) {
        __nv_bfloat16* base = sm + stage * stagesz;
        *(uint4*)(base + a_s * SLAB64 + a_r * SROW + a_h) = ra;
        #pragma unroll
        for (int it = 0; it < 2; it++) {
            int i = tid + it * 256;
            int s = i >> 8, rem = i & 255, r = rem >> 1, h = (rem & 1) * 8;
            *(uint4*)(base + 2 * SLAB64 + s * SLABE + r * SROW + h) = rb[it];
        }
        __syncthreads();

        if (k0 + 16 < ke) {
            ra = *(const uint4*)(Ag[a_s] + (size_t)(bm + a_r) * H_ + k0 + 16 + a_h);
            #pragma unroll
            for (int it = 0; it < 2; it++) {
                int i = tid + it * 256;
                int s = i >> 8, rem = i & 255, r = rem >> 1, h = (rem & 1) * 8;
                rb[it] = *(const uint4*)(Ag[s] + (size_t)(bn + r) * H_ + k0 + 16 + h);
            }
        }

        uint32_t af[2][2][4];
        #pragma unroll
        for (int s = 0; s < 2; s++) {
            const __nv_bfloat16* As_ = base + s * SLAB64;
            #pragma unroll
            for (int mi = 0; mi < 2; mi++) {
                const __nv_bfloat16* p = As_ + (wm * 32 + mi * 16 + lml) * SROW + lmk;
                ldsm4(af[s][mi][0], af[s][mi][1], af[s][mi][2], af[s][mi][3], p);
            }
        }
        uint32_t bfr[2][4][2];
        #pragma unroll
        for (int s = 0; s < 2; s++) {
            const __nv_bfloat16* Bs_ = base + 2 * SLAB64 + s * SLABE;
            #pragma unroll
            for (int h = 0; h < 2; h++) {
                const __nv_bfloat16* p = Bs_ + (wn * 32 + h * 16 + lml) * SROW + lmk;
                ldsm4(bfr[s][h * 2 + 0][0], bfr[s][h * 2 + 1][0],
                      bfr[s][h * 2 + 0][1], bfr[s][h * 2 + 1][1], p);
            }
        }

        #pragma unroll
        for (int mi = 0; mi < 2; mi++)
            #pragma unroll
            for (int ni = 0; ni < 4; ni++) {
                mma16816(acc[mi][ni], af[0][mi][0], af[0][mi][1], af[0][mi][2], af[0][mi][3],
                         bfr[0][ni][0], bfr[0][ni][1]);
                mma16816(acc[mi][ni], af[0][mi][0], af[0][mi][1], af[0][mi][2], af[0][mi][3],
                         bfr[1][ni][0], bfr[1][ni][1]);
                mma16816(acc[mi][ni], af[1][mi][0], af[1][mi][1], af[1][mi][2], af[1][mi][3],
                         bfr[0][ni][0], bfr[0][ni][1]);
            }
        __syncthreads();
        stage ^= 1;
    }

    #pragma unroll
    for (int mi = 0; mi < 2; mi++) {
        int r0 = bm + wm * 32 + mi * 16 + gid;
        #pragma unroll
        for (int ni = 0; ni < 4; ni++) {
            int c = bn + wn * 32 + ni * 8 + tid4 * 2;
            *(float2*)(Cout + (size_t)r0 * NSEG + c)       = make_float2(acc[mi][ni][0], acc[mi][ni][1]);
            *(float2*)(Cout + (size_t)(r0 + 8) * NSEG + c) = make_float2(acc[mi][ni][2], acc[mi][ni][3]);
        }
    }
}

// K3b: g_sdot = sum of KS_S partials (pruned rows). grid (64, B)
__global__ __launch_bounds__(256) void k_sdot_fix(const int* __restrict__ ind) {
    const int b    = blockIdx.y;
    const int qmax = ind[b * S_ + QPB - 1];
    const int row  = blockIdx.x * 4 + (threadIdx.x >> 6);
    if (row > qmax) return;
    const int c4   = threadIdx.x & 63;
    const size_t e = (size_t)row * 64 + c4;
    const size_t base = (size_t)b * KS_S * (NSEG * NSEG / 4);
    float4 s = make_float4(0.f, 0.f, 0.f, 0.f);
    #pragma unroll
    for (int ks = 0; ks < KS_S; ks++) {
        float4 p = ((const float4*)g_spart)[base + (size_t)ks * (NSEG * NSEG / 4) + e];
        s.x += p.x; s.y += p.y; s.z += p.z; s.w += p.w;
    }
    ((float4*)(g_sdot + (size_t)b * NSEG * NSEG))[e] = s;
}

// ---------------------------------------------------------------------------
// K4: per query row: masked logsumexp + argmax over 256 segments (vectorized)
// ---------------------------------------------------------------------------
__global__ __launch_bounds__(256) void k_rows(const int* __restrict__ ind,
                                              const int* __restrict__ clc) {
    __shared__ __align__(16) int s_cnt[NSEG];
    __shared__ __align__(16) int s_fst[NSEG];
    const int lane = threadIdx.x & 31;
    const int gw   = blockIdx.x * 8 + (threadIdx.x >> 5);
    const int b    = gw >> 9;
    const int i    = gw & (QPB - 1);

    if (threadIdx.x < NSEG) {
        s_cnt[threadIdx.x] = g_cnt  [b * NSEG + threadIdx.x];
        s_fst[threadIdx.x] = g_first[b * NSEG + threadIdx.x];
    }
    __syncthreads();

    const int q     = ind[b * S_ + i];
    const int label = clc[b * S_ + i];
    const float* srow = g_sdot + ((size_t)b * NSEG + q) * NSEG;

    float s[8]; int c[8]; int f[8];
    #pragma unroll
    for (int t = 0; t < 2; t++) {
        int v4 = lane + 32 * t;
        float4 sv = __ldg((const float4*)srow + v4);
        int4   cv = ((const int4*)s_cnt)[v4];
        int4   fv = ((const int4*)s_fst)[v4];
        s[4 * t + 0] = sv.x; s[4 * t + 1] = sv.y; s[4 * t + 2] = sv.z; s[4 * t + 3] = sv.w;
        c[4 * t + 0] = cv.x; c[4 * t + 1] = cv.y; c[4 * t + 2] = cv.z; c[4 * t + 3] = cv.w;
        f[4 * t + 0] = fv.x; f[4 * t + 1] = fv.y; f[4 * t + 2] = fv.z; f[4 * t + 3] = fv.w;
    }

    float bmax = -INFINITY; int bj = 0x7fffffff;
    #pragma unroll
    for (int t = 0; t < 8; t++) {
        if (c[t] > 0) {
            if (s[t] > bmax || (s[t] == bmax && f[t] < bj)) { bmax = s[t]; bj = f[t]; }
        }
    }
    #pragma unroll
    for (int off = 16; off; off >>= 1) {
        float os = __shfl_xor_sync(0xffffffffu, bmax, off);
        int   oj = __shfl_xor_sync(0xffffffffu, bj,   off);
        if (os > bmax || (os == bmax && oj < bj)) { bmax = os; bj = oj; }
    }

    float z = 0.0f;
    #pragma unroll
    for (int t = 0; t < 8; t++)
        if (c[t] > 0) z += (float)c[t] * expf(s[t] - bmax);
    #pragma unroll
    for (int off = 16; off; off >>= 1)
        z += __shfl_xor_sync(0xffffffffu, z, off);

    if (lane == 0) {
        int vlab = ind[b * S_ + label];
        float slab = __ldg(srow + vlab);
        float loss = (logf(z) + bmax) - slab;
        if (label < HALF) loss += 1.0e9f;
        g_loss[gw] = loss;
        g_corr[gw] = (bj == label) ? 1 : 0;
    }
}

// ---------------------------------------------------------------------------
// K5: final reduction -> 6 scalars
// ---------------------------------------------------------------------------
__global__ __launch_bounds__(256) void k_final(float* __restrict__ out) {
    __shared__ double sls[256], slt[256];
    __shared__ int    scs[256], sct[256];
    const int t = threadIdx.x;
    double ls = 0.0, lt = 0.0;
    int cs = 0, ct = 0;
    for (int r = t; r < NROWS; r += 256) {
        if (r & 1) { lt += (double)g_loss[r]; ct += g_corr[r]; }
        else       { ls += (double)g_loss[r]; cs += g_corr[r]; }
    }
    sls[t] = ls; slt[t] = lt; scs[t] = cs; sct[t] = ct;
    __syncthreads();
    for (int off = 128; off; off >>= 1) {
        if (t < off) {
            sls[t] += sls[t + off]; slt[t] += slt[t + off];
            scs[t] += scs[t + off]; sct[t] += sct[t + off];
        }
        __syncthreads();
    }
    if (t == 0) {
        const double n = (double)(NROWS / 2);
        out[0] = (float)(sls[0] / n);
        out[1] = (float)scs[0];
        out[2] = (float)(n + 1e-6);
        out[3] = (float)(slt[0] / n);
        out[4] = (float)sct[0];
        out[5] = (float)(n + 1e-6);
    }
}

// ---------------------------------------------------------------------------
extern "C" void kernel_launch(void* const* d_in, const int* in_sizes, int n_in,
                              void* d_out, int out_size) {
    const float* x    = (const float*)d_in[0];
    const float* W    = (const float*)d_in[1];
    const float* bias = (const float*)d_in[2];
    const int*   ind  = (const int*)  d_in[3];
    const int*   clc  = (const int*)  d_in[4];
    float* out = (float*)d_out;
    (void)in_sizes; (void)n_in; (void)out_size;

    static bool attr_set = false;
    if (!attr_set) {
        cudaFuncSetAttribute(k_proj_mma, cudaFuncAttributeMaxDynamicSharedMemorySize, SMEM_MMA);
        cudaFuncSetAttribute(k_sdot_mma, cudaFuncAttributeMaxDynamicSharedMemorySize, SMEM_M64);
        attr_set = true;
    }

    k_prep<<<NCONVW + NSEG * B_, 256>>>(x, W, ind);

    dim3 g2(H_ / 128, (B_ * NSEG) / 128, KS_P);      // (6, 8, 3) = 144 blocks
    k_proj_mma<<<g2, 256, SMEM_MMA>>>();
    k_proj_fix<<<(B_ * NSEG * H_ / 4) / 512, 256>>>(bias);

    dim3 g3(NSEG / 128, NSEG / 64, B_ * KS_S);       // (2, 4, 48)
    k_sdot_mma<<<g3, 256, SMEM_M64>>>(ind);
    dim3 g3f(64, B_);
    k_sdot_fix<<<g3f, 256>>>(ind);

    k_rows<<<NROWS / 8, 256>>>(ind, clc);

    k_final<<<1, 256>>>(out);
}